// round 13
// baseline (speedup 1.0000x reference)
#include <cuda_runtime.h>
#include <cuda_fp16.h>
#include <math.h>
#include <stdint.h>

// ---------------- problem constants ----------------
#define N0    120000
#define E0    600000
#define N1    30000
#define E1    150000
#define N2    8000
#define DIN   768
#define HID   512
#define RREL  5
#define HEADS 4
#define DH    128
#define OUTC  153
#define EPSBN 1e-5f

#define NBINS0 (N1 * RREL)
#define NBINS1 (N2 * RREL)
#define NBINSA (NBINS0 + NBINS1)

// ---------------- static scratch ----------------
__device__ __half   g_aggX[(size_t)N1 * HEADS * RREL * DIN];
__device__ uint32_t g_BcatP[(size_t)HEADS * ((RREL * DIN + DIN) / 2) * DH];
__device__ __half   g_xh[(size_t)N0 * DIN];     // all of x in fp16
__device__ __half   g_oh[(size_t)N1 * HID];     // out0 in fp16 (post-BN)
__device__ float g_SS[(size_t)N0 * 40];
__device__ float g_out0[(size_t)N1 * HID];
__device__ float g_out1[(size_t)N2 * HID];
__device__ float g_z[(size_t)N2 * HID];
__device__ float g_alpha0[(size_t)E0 * 4];
__device__ float g_alpha1[(size_t)E1 * 4];
__device__ float g_den[(size_t)NBINSA * 4];
__device__ float g_C[DIN * 40];
__device__ float g_bias[HID];
__device__ float g_ps[64 * HID];
__device__ float g_pq[64 * HID];
__device__ float g_mu[HID];
__device__ float g_rstd[HID];
__device__ int   g_rowptr[NBINSA + 1];
__device__ int   g_perm[E0 + E1];
__device__ int   g_cnt[NBINSA];
__device__ int   g_incl[NBINSA];
__device__ int   g_bsum[1026];

// ---------------- tf32 / fp16 helpers ----------------
__device__ __forceinline__ uint32_t f2tf32(float x) {
    uint32_t u;
    asm("cvt.rna.tf32.f32 %0, %1;" : "=r"(u) : "f"(x));
    return u;
}

__device__ __forceinline__ void mma_tf32(float* d, const uint32_t* a, const uint32_t* b) {
    asm volatile(
        "mma.sync.aligned.m16n8k8.row.col.f32.tf32.tf32.f32 "
        "{%0,%1,%2,%3}, {%4,%5,%6,%7}, {%8,%9}, {%0,%1,%2,%3};\n"
        : "+f"(d[0]), "+f"(d[1]), "+f"(d[2]), "+f"(d[3])
        : "r"(a[0]), "r"(a[1]), "r"(a[2]), "r"(a[3]), "r"(b[0]), "r"(b[1]));
}

__device__ __forceinline__ void mma_f16(float* d, const uint32_t* a, const uint32_t* b) {
    asm volatile(
        "mma.sync.aligned.m16n8k16.row.col.f32.f16.f16.f32 "
        "{%0,%1,%2,%3}, {%4,%5,%6,%7}, {%8,%9}, {%0,%1,%2,%3};\n"
        : "+f"(d[0]), "+f"(d[1]), "+f"(d[2]), "+f"(d[3])
        : "r"(a[0]), "r"(a[1]), "r"(a[2]), "r"(a[3]), "r"(b[0]), "r"(b[1]));
}

// ---------------- merged CSR build ----------------
__global__ void hist2(const int* __restrict__ ed0, const int* __restrict__ et0,
                      const int* __restrict__ ed1, const int* __restrict__ et1,
                      int* __restrict__ cnt) {
    int i = blockIdx.x * blockDim.x + threadIdx.x;
    if (i < E0) {
        atomicAdd(&cnt[ed0[i] * RREL + et0[i]], 1);
    } else if (i < E0 + E1) {
        int e = i - E0;
        atomicAdd(&cnt[NBINS0 + ed1[e] * RREL + et1[e]], 1);
    }
}

__global__ void scan1(const int* __restrict__ cnt, int* __restrict__ incl,
                      int* __restrict__ bsum, int n) {
    __shared__ int sh[256];
    int t = threadIdx.x;
    int i = blockIdx.x * 256 + t;
    int v = (i < n) ? cnt[i] : 0;
    sh[t] = v;
    __syncthreads();
    #pragma unroll
    for (int off = 1; off < 256; off <<= 1) {
        int a = (t >= off) ? sh[t - off] : 0;
        __syncthreads();
        sh[t] += a;
        __syncthreads();
    }
    if (i < n) incl[i] = sh[t];
    if (t == 255) bsum[blockIdx.x] = sh[255];
}

__global__ void scan2(int* __restrict__ bsum, int nb) {
    __shared__ int sh[1024];
    int t = threadIdx.x;
    int v = (t < nb) ? bsum[t] : 0;
    sh[t] = v;
    __syncthreads();
    #pragma unroll
    for (int off = 1; off < 1024; off <<= 1) {
        int a = (t >= off) ? sh[t - off] : 0;
        __syncthreads();
        sh[t] += a;
        __syncthreads();
    }
    if (t < nb) bsum[t] = sh[t] - v;
    if (t == nb - 1) bsum[nb] = sh[t];
}

__global__ void scan3(const int* __restrict__ incl, const int* __restrict__ cnt,
                      const int* __restrict__ bsum, int* __restrict__ rowptr, int n) {
    int i = blockIdx.x * 256 + threadIdx.x;
    if (i < n) rowptr[i] = bsum[i >> 8] + incl[i] - cnt[i];
    if (i == 0) rowptr[n] = bsum[(n + 255) >> 8];
}

__global__ void scatter2(const int* __restrict__ ed0, const int* __restrict__ et0,
                         const int* __restrict__ ed1, const int* __restrict__ et1,
                         const int* __restrict__ rowptr,
                         int* __restrict__ cur, int* __restrict__ perm) {
    int i = blockIdx.x * blockDim.x + threadIdx.x;
    int bin, loc;
    if (i < E0) {
        bin = ed0[i] * RREL + et0[i];
        loc = i;
    } else if (i < E0 + E1) {
        int e = i - E0;
        bin = NBINS0 + ed1[e] * RREL + et1[e];
        loc = e;
    } else return;
    int p = atomicAdd(&cur[bin], 1);
    perm[rowptr[bin] + p] = loc;
}

// ---------------- combined score projection ----------------
__global__ void cmb_kernel(const float* __restrict__ W, const float* __restrict__ as_,
                           const float* __restrict__ ad_, float* __restrict__ C, int K) {
    int gw = (blockIdx.x * blockDim.x + threadIdx.x) >> 5;
    int lane = threadIdx.x & 31;
    if (gw >= K * 40) return;
    int k = gw / 40, col = gw % 40;
    int jh = (col < 20) ? col : col - 20;
    int j = jh / 4, h = jh % 4;
    const float* a = ((col < 20) ? as_ : ad_) + (size_t)(j * 4 + h) * DH;
    const float* w = W + ((size_t)j * K + k) * HID + h * DH;
    float s = 0.f;
    #pragma unroll
    for (int d = lane; d < DH; d += 32) s += w[d] * a[d];
    for (int off = 16; off; off >>= 1) s += __shfl_xor_sync(0xffffffffu, s, off);
    if (lane == 0) C[k * 40 + col] = s;
}

__global__ void biasvec_kernel(const float* __restrict__ bsk, const float* __restrict__ b,
                               float* __restrict__ out) {
    int t = threadIdx.x;
    float s = bsk[t];
    for (int j = 0; j < RREL; j++) s += b[j * HID + t];
    out[t] = s;
}

__global__ void f2h_kernel(const float* __restrict__ src, __half* __restrict__ dst, int n) {
    int i = blockIdx.x * blockDim.x + threadIdx.x;
    if (i < n) dst[i] = __float2half_rn(src[i]);
}

// pack per head, k-pair layout
__global__ void prepack_h(const float* __restrict__ W, const float* __restrict__ Wsk,
                          uint32_t* __restrict__ Bp, int K, int KX) {
    int idx = blockIdx.x * blockDim.x + threadIdx.x;
    int kt2 = (RREL * K + KX) / 2;
    int total = HEADS * kt2 * DH;
    if (idx >= total) return;
    int n = idx & (DH - 1);
    int rest = idx >> 7;
    int kp = rest % kt2;
    int h = rest / kt2;
    float v[2];
    #pragma unroll
    for (int q = 0; q < 2; q++) {
        int k = 2 * kp + q;
        if (k < RREL * K) {
            int j = k / K, kk = k % K;
            v[q] = W[((size_t)j * K + kk) * HID + h * DH + n];
        } else {
            v[q] = Wsk[(size_t)(k - RREL * K) * HID + h * DH + n];
        }
    }
    __half2 p = __halves2half2(__float2half_rn(v[0]), __float2half_rn(v[1]));
    Bp[idx] = *(uint32_t*)&p;
}

// ---------------- mma.sync tf32 GEMM ----------------
template <int BN>
__global__ void __launch_bounds__(256, 2) tgemm(
    const float* __restrict__ A, int lda, size_t hsA,
    const float* __restrict__ B, size_t hsB,
    float* __restrict__ C, int ldc, size_t hsC,
    int M, int N, int K, const float* __restrict__ bias, int accum) {
    constexpr int MF  = (BN == 128) ? 4 : 2;
    constexpr int NQ  = BN / 4;
    constexpr int ITB = BN / 64;
    __shared__ uint32_t As[2][16 * 128];
    __shared__ uint32_t Bs[2][16 * BN];
    A += (size_t)blockIdx.z * hsA;
    B += (size_t)blockIdx.z * hsB;
    C += (size_t)blockIdx.z * hsC;
    const int bm = blockIdx.y * 128, bn = blockIdx.x * BN;
    const int tid = threadIdx.x;
    const int lane = tid & 31, warp = tid >> 5;
    const int wm = (BN == 128) ? (warp >> 2) * 64 : (warp >> 1) * 32;
    const int wn = (BN == 128) ? (warp & 3) * 32 : (warp & 1) * 32;
    const int g = lane >> 2, ctg = lane & 3;
    const bool n_vec = ((N & 3) == 0);

    float acc[MF][4][4];
    #pragma unroll
    for (int mf = 0; mf < MF; mf++)
        #pragma unroll
        for (int nf = 0; nf < 4; nf++)
            #pragma unroll
            for (int q = 0; q < 4; q++) acc[mf][nf][q] = 0.f;

    float4 aReg[2];
    float  bReg[ITB][4];

    auto fetch = [&](int k0) {
        #pragma unroll
        for (int it = 0; it < 2; it++) {
            int idx = tid + it * 256;
            int r = idx >> 2, c4 = idx & 3;
            int gr = bm + r;
            aReg[it] = make_float4(0.f, 0.f, 0.f, 0.f);
            if (gr < M) aReg[it] = *(const float4*)(A + (size_t)gr * lda + k0 + c4 * 4);
        }
        #pragma unroll
        for (int it = 0; it < ITB; it++) {
            int idx = tid + it * 256;
            int kk = idx / NQ, nq = idx % NQ;
            int gn = bn + nq * 4;
            const float* bp = B + (size_t)(k0 + kk) * N + gn;
            bReg[it][0] = bReg[it][1] = bReg[it][2] = bReg[it][3] = 0.f;
            if (n_vec && gn + 3 < N) {
                float4 v = *(const float4*)bp;
                bReg[it][0] = v.x; bReg[it][1] = v.y; bReg[it][2] = v.z; bReg[it][3] = v.w;
            } else {
                if (gn < N)     bReg[it][0] = bp[0];
                if (gn + 1 < N) bReg[it][1] = bp[1];
                if (gn + 2 < N) bReg[it][2] = bp[2];
                if (gn + 3 < N) bReg[it][3] = bp[3];
            }
        }
    };

    auto stage = [&](int buf) {
        #pragma unroll
        for (int it = 0; it < 2; it++) {
            int idx = tid + it * 256;
            int r = idx >> 2, c4 = idx & 3;
            uint32_t uv[4] = {f2tf32(aReg[it].x), f2tf32(aReg[it].y),
                              f2tf32(aReg[it].z), f2tf32(aReg[it].w)};
            #pragma unroll
            for (int s = 0; s < 4; s++) {
                int i = (s + lane) & 3;
                int kk = c4 * 4 + i;
                As[buf][kk * 128 + (r ^ (8 * (kk & 3)))] = uv[i];
            }
        }
        #pragma unroll
        for (int it = 0; it < ITB; it++) {
            int idx = tid + it * 256;
            int kk = idx / NQ, nq = idx % NQ;
            *(uint4*)&Bs[buf][kk * BN + ((nq * 4) ^ (8 * (kk & 3)))] =
                make_uint4(f2tf32(bReg[it][0]), f2tf32(bReg[it][1]),
                           f2tf32(bReg[it][2]), f2tf32(bReg[it][3]));
        }
    };

    const int nk = K >> 4;
    fetch(0);
    stage(0);
    if (nk > 1) fetch(16);
    __syncthreads();

    for (int ki = 0; ki < nk; ki++) {
        const int cur = ki & 1;
        if (ki + 1 < nk) {
            stage(cur ^ 1);
            if (ki + 2 < nk) fetch((ki + 2) << 4);
        }

        #pragma unroll
        for (int ks = 0; ks < 16; ks += 8) {
            uint32_t af[MF][4], bf[4][2];
            int kA0 = ks + ctg;
            int kA1 = ks + 4 + ctg;
            #pragma unroll
            for (int mf = 0; mf < MF; mf++) {
                int row = wm + mf * 16 + g;
                af[mf][0] = As[cur][kA0 * 128 + (row ^ (8 * ctg))];
                af[mf][1] = As[cur][kA0 * 128 + ((row + 8) ^ (8 * ctg))];
                af[mf][2] = As[cur][kA1 * 128 + (row ^ (8 * ctg))];
                af[mf][3] = As[cur][kA1 * 128 + ((row + 8) ^ (8 * ctg))];
            }
            #pragma unroll
            for (int nf = 0; nf < 4; nf++) {
                int col = wn + nf * 8 + g;
                bf[nf][0] = Bs[cur][kA0 * BN + (col ^ (8 * ctg))];
                bf[nf][1] = Bs[cur][kA1 * BN + (col ^ (8 * ctg))];
            }
            #pragma unroll
            for (int mf = 0; mf < MF; mf++)
                #pragma unroll
                for (int nf = 0; nf < 4; nf++)
                    mma_tf32(acc[mf][nf], af[mf], bf[nf]);
        }
        __syncthreads();
    }

    #pragma unroll
    for (int mf = 0; mf < MF; mf++) {
        #pragma unroll
        for (int half = 0; half < 2; half++) {
            int r = bm + wm + mf * 16 + g + half * 8;
            if (r >= M) continue;
            #pragma unroll
            for (int nf = 0; nf < 4; nf++) {
                int c = bn + wn + nf * 8 + ctg * 2;
                float v0 = acc[mf][nf][half * 2 + 0];
                float v1 = acc[mf][nf][half * 2 + 1];
                if (c < N) {
                    float base0 = accum ? C[(size_t)r * ldc + c] : 0.f;
                    C[(size_t)r * ldc + c] = base0 + v0 + (bias ? bias[c] : 0.f);
                }
                if (c + 1 < N) {
                    float base1 = accum ? C[(size_t)r * ldc + c + 1] : 0.f;
                    C[(size_t)r * ldc + c + 1] = base1 + v1 + (bias ? bias[c + 1] : 0.f);
                }
            }
        }
    }
}

// ---------------- fp16 cp.async head GEMM, BK=64, fused skip ----------------
#define ASH 36
#define BSH 136
#define HGH_SMEM (2 * (128 * ASH + 32 * BSH) * 4)

__global__ void __launch_bounds__(256, 2) hgemm(
    const __half* __restrict__ A1, int lda1, size_t hsA1,
    const __half* __restrict__ A2, int lda2,
    const uint32_t* __restrict__ Bp, size_t hsB,
    float* __restrict__ C, int ldc, size_t hsC,
    int M, int KA, int KX, const float* __restrict__ bias) {
    extern __shared__ uint32_t smu[];
    uint32_t* Asm[2] = {smu, smu + 128 * ASH};
    uint32_t* Bsm[2] = {smu + 2 * 128 * ASH, smu + 2 * 128 * ASH + 32 * BSH};
    A1 += (size_t)blockIdx.y * hsA1;
    Bp += (size_t)blockIdx.y * hsB;
    C  += (size_t)blockIdx.y * hsC;
    bias += (size_t)blockIdx.y * DH;
    const int bm = blockIdx.x * 128;
    const int tid = threadIdx.x, lane = tid & 31, warp = tid >> 5;
    const int wm = (warp >> 2) * 64, wn = (warp & 3) * 32;
    const int g = lane >> 2, ctg = lane & 3;

    float acc[4][4][4];
    #pragma unroll
    for (int mf = 0; mf < 4; mf++)
        #pragma unroll
        for (int nf = 0; nf < 4; nf++)
            #pragma unroll
            for (int q = 0; q < 4; q++) acc[mf][nf][q] = 0.f;

    auto issue = [&](int buf, int k0) {
        const __half* Ab;
        int ldx, kc;
        if (k0 < KA) { Ab = A1; ldx = lda1; kc = k0; }
        else         { Ab = A2; ldx = lda2; kc = k0 - KA; }
        #pragma unroll
        for (int it = 0; it < 4; it++) {
            int idx = tid + it * 256;
            int r = idx >> 3, c8 = idx & 7;
            const __half* src = Ab + (size_t)(bm + r) * ldx + kc + c8 * 8;
            uint32_t dst = (uint32_t)__cvta_generic_to_shared(&Asm[buf][r * ASH + c8 * 4]);
            int sz = (bm + r < M) ? 16 : 0;
            asm volatile("cp.async.cg.shared.global [%0], [%1], 16, %2;"
                         :: "r"(dst), "l"(src), "r"(sz));
        }
        int kp0 = k0 >> 1;
        #pragma unroll
        for (int it = 0; it < 4; it++) {
            int idx = tid + it * 256;
            int kp = idx >> 5, nq = idx & 31;
            const uint32_t* src = Bp + (size_t)(kp0 + kp) * 128 + nq * 4;
            uint32_t dst = (uint32_t)__cvta_generic_to_shared(&Bsm[buf][kp * BSH + nq * 4]);
            asm volatile("cp.async.cg.shared.global [%0], [%1], 16;" :: "r"(dst), "l"(src));
        }
        asm volatile("cp.async.commit_group;");
    };

    const int nk = (KA + KX) >> 6;
    issue(0, 0);
    issue(1, 64);
    asm volatile("cp.async.wait_group 1;");
    __syncthreads();

    for (int ki = 0; ki < nk; ki++) {
        const int cur = ki & 1;
        const uint32_t* Ab = Asm[cur];
        const uint32_t* Bb = Bsm[cur];

        #pragma unroll
        for (int kc2 = 0; kc2 < 4; kc2++) {
            int kb = kc2 * 8;
            uint32_t af[4][4], bf[4][2];
            #pragma unroll
            for (int mf = 0; mf < 4; mf++) {
                int row = wm + mf * 16 + g;
                af[mf][0] = Ab[row * ASH + kb + ctg];
                af[mf][1] = Ab[(row + 8) * ASH + kb + ctg];
                af[mf][2] = Ab[row * ASH + kb + 4 + ctg];
                af[mf][3] = Ab[(row + 8) * ASH + kb + 4 + ctg];
            }
            #pragma unroll
            for (int nf = 0; nf < 4; nf++) {
                int col = wn + nf * 8 + g;
                bf[nf][0] = Bb[(kb + ctg) * BSH + col];
                bf[nf][1] = Bb[(kb + 4 + ctg) * BSH + col];
            }
            #pragma unroll
            for (int mf = 0; mf < 4; mf++)
                #pragma unroll
                for (int nf = 0; nf < 4; nf++)
                    mma_f16(acc[mf][nf], af[mf], bf[nf]);
        }

        __syncthreads();
        if (ki + 2 < nk) issue(cur, (ki + 2) << 6);
        if (ki + 1 < nk) {
            if (ki + 2 < nk) asm volatile("cp.async.wait_group 1;");
            else             asm volatile("cp.async.wait_group 0;");
            __syncthreads();
        }
    }

    #pragma unroll
    for (int mf = 0; mf < 4; mf++) {
        #pragma unroll
        for (int half = 0; half < 2; half++) {
            int r = bm + wm + mf * 16 + g + half * 8;
            if (r >= M) continue;
            float* cr = C + (size_t)r * ldc;
            #pragma unroll
            for (int nf = 0; nf < 4; nf++) {
                int c = wn + nf * 8 + ctg * 2;
                cr[c]     = acc[mf][nf][half * 2 + 0] + bias[c];
                cr[c + 1] = acc[mf][nf][half * 2 + 1] + bias[c + 1];
            }
        }
    }
}

// ---------------- single-pass unnormalized softmax ----------------
__global__ void alpha_kernel(const int* __restrict__ rowptr, const int* __restrict__ perm,
                             const int* __restrict__ esrc,
                             const float* __restrict__ SS, float* __restrict__ alpha,
                             float* __restrict__ den, int ndst) {
    int d = blockIdx.x * 8 + (threadIdx.x >> 5);
    if (d >= ndst) return;
    int lane = threadIdx.x & 31;
    for (int j = 0; j < RREL; j++) {
        int bin = d * RREL + j;
        int beg = rowptr[bin], end = rowptr[bin + 1];
        float sd[4];
        #pragma unroll
        for (int h = 0; h < 4; h++) sd[h] = SS[(size_t)d * 40 + 20 + j * 4 + h];

        float sm[4] = {0.f, 0.f, 0.f, 0.f};
        for (int i = beg + lane; i < end; i += 32) {
            int e = perm[i];
            int s = esrc[e];
            float ex[4];
            #pragma unroll
            for (int h = 0; h < 4; h++) {
                float sc = SS[(size_t)s * 40 + j * 4 + h] + sd[h];
                sc = sc > 0.f ? sc : 0.2f * sc;
                ex[h] = expf(sc);
                sm[h] += ex[h];
            }
            *(float4*)(alpha + (size_t)e * 4) = make_float4(ex[0], ex[1], ex[2], ex[3]);
        }
        #pragma unroll
        for (int h = 0; h < 4; h++)
            for (int off = 16; off; off >>= 1)
                sm[h] += __shfl_xor_sync(0xffffffffu, sm[h], off);
        if (lane == 0)
            *(float4*)(den + (size_t)bin * 4) = make_float4(sm[0], sm[1], sm[2], sm[3]);
    }
}

// ---------------- aggregate: fp16 gather, fused 1/denom, half2 stores ----------------
template <int DIN_>
__global__ void __launch_bounds__(DIN_ / 4) aggx_kernel(
    const int* __restrict__ rowptr, const int* __restrict__ perm,
    const int* __restrict__ esrc,
    const float* __restrict__ alpha, const float* __restrict__ den,
    const __half* __restrict__ Xh, __half* __restrict__ aggX) {
    int d = blockIdx.x, t = threadIdx.x;   // t < DIN_/4
    #pragma unroll
    for (int j = 0; j < RREL; j++) {
        int bin = d * RREL + j;
        float acc[HEADS][4];
        #pragma unroll
        for (int h = 0; h < HEADS; h++)
            #pragma unroll
            for (int c = 0; c < 4; c++) acc[h][c] = 0.f;

        int beg = rowptr[bin], end = rowptr[bin + 1];
        for (int i = beg; i < end; i++) {
            int e = perm[i];
            int s = esrc[e];
            float4 al = *(const float4*)(alpha + (size_t)e * 4);
            uint2 pk = *(const uint2*)(Xh + (size_t)s * DIN_ + t * 4);
            float2 f0 = __half22float2(*(__half2*)&pk.x);
            float2 f1 = __half22float2(*(__half2*)&pk.y);
            float xv0 = f0.x, xv1 = f0.y, xv2 = f1.x, xv3 = f1.y;
            acc[0][0] += al.x * xv0; acc[0][1] += al.x * xv1;
            acc[0][2] += al.x * xv2; acc[0][3] += al.x * xv3;
            acc[1][0] += al.y * xv0; acc[1][1] += al.y * xv1;
            acc[1][2] += al.y * xv2; acc[1][3] += al.y * xv3;
            acc[2][0] += al.z * xv0; acc[2][1] += al.z * xv1;
            acc[2][2] += al.z * xv2; acc[2][3] += al.z * xv3;
            acc[3][0] += al.w * xv0; acc[3][1] += al.w * xv1;
            acc[3][2] += al.w * xv2; acc[3][3] += al.w * xv3;
        }
        float4 dn = *(const float4*)(den + (size_t)bin * 4);
        float rs[4] = {1.f / fmaxf(dn.x, 1e-16f), 1.f / fmaxf(dn.y, 1e-16f),
                       1.f / fmaxf(dn.z, 1e-16f), 1.f / fmaxf(dn.w, 1e-16f)};
        #pragma unroll
        for (int h = 0; h < HEADS; h++) {
            __half2 p0 = __halves2half2(__float2half_rn(acc[h][0] * rs[h]),
                                        __float2half_rn(acc[h][1] * rs[h]));
            __half2 p1 = __halves2half2(__float2half_rn(acc[h][2] * rs[h]),
                                        __float2half_rn(acc[h][3] * rs[h]));
            uint2 pk = make_uint2(*(uint32_t*)&p0, *(uint32_t*)&p1);
            *(uint2*)(aggX + ((size_t)(d * 4 + h)) * (RREL * DIN_) + j * DIN_ + t * 4) = pk;
        }
    }
}

// ---------------- batch-norm (partial-sum slab, no memset/atomics) ----------------
__global__ void bn_stats(const float* __restrict__ X, int n,
                         float* __restrict__ ps, float* __restrict__ pq) {
    int t = threadIdx.x;
    int rpb = (n + gridDim.x - 1) / gridDim.x;
    int r0 = blockIdx.x * rpb;
    int r1 = min(n, r0 + rpb);
    float s = 0.f, q = 0.f;
    for (int r = r0; r < r1; r++) {
        float v = X[(size_t)r * HID + t];
        s += v;
        q += v * v;
    }
    ps[blockIdx.x * HID + t] = s;
    pq[blockIdx.x * HID + t] = q;
}

__global__ void bn_final(const float* __restrict__ ps, const float* __restrict__ pq,
                         float n, float* __restrict__ mu, float* __restrict__ rstd) {
    int t = threadIdx.x;
    float s = 0.f, q = 0.f;
    #pragma unroll 8
    for (int b = 0; b < 64; b++) {
        s += ps[b * HID + t];
        q += pq[b * HID + t];
    }
    float m = s / n;
    float v = q / n - m * m;
    mu[t] = m;
    rstd[t] = rsqrtf(v + EPSBN);
}

__global__ void bn_apply(float* __restrict__ X, int n,
                         const float* __restrict__ g, const float* __restrict__ be,
                         const float* __restrict__ mu, const float* __restrict__ rstd, int act) {
    int idx = blockIdx.x * blockDim.x + threadIdx.x;
    int total = n * HID;
    if (idx >= total) return;
    int c = idx & (HID - 1);
    float v = X[idx];
    float y = g[c] * ((v - mu[c]) * rstd[c]) + be[c];
    X[idx] = (act == 0) ? (y > 0.f ? y : expm1f(y)) : fmaxf(y, 0.f);
}

// ---------------- host orchestration ----------------
static inline dim3 tg(int M, int N, int BN_, int Z = 1) {
    return dim3((N + BN_ - 1) / BN_, (M + 127) / 128, Z);
}

extern "C" void kernel_launch(void* const* d_in, const int* in_sizes, int n_in,
                              void* d_out, int out_size) {
    const float* x    = (const float*)d_in[0];
    const int*   es0  = (const int*)d_in[1];
    const int*   ed0  = (const int*)d_in[2];
    const int*   et0  = (const int*)d_in[3];
    const int*   es1  = (const int*)d_in[4];
    const int*   ed1  = (const int*)d_in[5];
    const int*   et1  = (const int*)d_in[6];
    const float* W0   = (const float*)d_in[7];
    const float* as0  = (const float*)d_in[8];
    const float* ad0  = (const float*)d_in[9];
    const float* b0   = (const float*)d_in[10];
    const float* Wsk0 = (const float*)d_in[11];
    const float* bsk0 = (const float*)d_in[12];
    const float* g0   = (const float*)d_in[13];
    const float* be0  = (const float*)d_in[14];
    const float* W1   = (const float*)d_in[15];
    const float* as1  = (const float*)d_in[16];
    const float* ad1  = (const float*)d_in[17];
    const float* b1   = (const float*)d_in[18];
    const float* Wsk1 = (const float*)d_in[19];
    const float* bsk1 = (const float*)d_in[20];
    const float* g1   = (const float*)d_in[21];
    const float* be1  = (const float*)d_in[22];
    const float* Wm1  = (const float*)d_in[23];
    const float* bm1  = (const float*)d_in[24];
    const float* gm   = (const float*)d_in[25];
    const float* bmn  = (const float*)d_in[26];
    const float* Wm2  = (const float*)d_in[27];
    const float* bm2  = (const float*)d_in[28];
    float* out = (float*)d_out;

    void *pAgg, *pBcP, *pXh, *pOh, *pSS, *pOut0, *pOut1, *pZ, *pA0, *pA1, *pDen, *pC, *pBias;
    void *pPS, *pPQ, *pMu, *pRs, *pRp, *pPerm, *pCnt, *pIncl, *pBsum;
    cudaGetSymbolAddress(&pAgg, g_aggX);
    cudaGetSymbolAddress(&pBcP, g_BcatP);
    cudaGetSymbolAddress(&pXh, g_xh);
    cudaGetSymbolAddress(&pOh, g_oh);
    cudaGetSymbolAddress(&pSS, g_SS);
    cudaGetSymbolAddress(&pOut0, g_out0);
    cudaGetSymbolAddress(&pOut1, g_out1);
    cudaGetSymbolAddress(&pZ, g_z);
    cudaGetSymbolAddress(&pA0, g_alpha0);
    cudaGetSymbolAddress(&pA1, g_alpha1);
    cudaGetSymbolAddress(&pDen, g_den);
    cudaGetSymbolAddress(&pC, g_C);
    cudaGetSymbolAddress(&pBias, g_bias);
    cudaGetSymbolAddress(&pPS, g_ps);
    cudaGetSymbolAddress(&pPQ, g_pq);
    cudaGetSymbolAddress(&pMu, g_mu);
    cudaGetSymbolAddress(&pRs, g_rstd);
    cudaGetSymbolAddress(&pRp, g_rowptr);
    cudaGetSymbolAddress(&pPerm, g_perm);
    cudaGetSymbolAddress(&pCnt, g_cnt);
    cudaGetSymbolAddress(&pIncl, g_incl);
    cudaGetSymbolAddress(&pBsum, g_bsum);

    __half* aggX    = (__half*)pAgg;
    uint32_t* BcatP = (uint32_t*)pBcP;
    __half* xh      = (__half*)pXh;
    __half* oh      = (__half*)pOh;
    float* SS   = (float*)pSS;
    float* out0 = (float*)pOut0;
    float* out1 = (float*)pOut1;
    float* z    = (float*)pZ;
    float* a0   = (float*)pA0;
    float* a1   = (float*)pA1;
    float* den  = (float*)pDen;
    float* C    = (float*)pC;
    float* bias = (float*)pBias;
    float* ps   = (float*)pPS;
    float* pq   = (float*)pPQ;
    float* mu   = (float*)pMu;
    float* rstd = (float*)pRs;
    int* rp     = (int*)pRp;
    int* perm   = (int*)pPerm;
    int* cnt    = (int*)pCnt;
    int* incl   = (int*)pIncl;
    int* bsum   = (int*)pBsum;

    cudaStream_t st = 0;
    const int NBA = (NBINSA + 255) / 256;
    const int EA  = E0 + E1;

    cudaFuncSetAttribute(hgemm, cudaFuncAttributeMaxDynamicSharedMemorySize, HGH_SMEM);

    // ===== merged CSR (both layers) + x -> fp16 =====
    cudaMemsetAsync(cnt, 0, NBINSA * sizeof(int), st);
    hist2<<<(EA + 255) / 256, 256, 0, st>>>(ed0, et0, ed1, et1, cnt);
    scan1<<<NBA, 256, 0, st>>>(cnt, incl, bsum, NBINSA);
    scan2<<<1, 1024, 0, st>>>(bsum, NBA);
    scan3<<<NBA, 256, 0, st>>>(incl, cnt, bsum, rp, NBINSA);
    cudaMemsetAsync(cnt, 0, NBINSA * sizeof(int), st);
    scatter2<<<(EA + 255) / 256, 256, 0, st>>>(ed0, et0, ed1, et1, rp, cnt, perm);
    f2h_kernel<<<((int)((size_t)N0 * DIN) + 255) / 256, 256, 0, st>>>(x, xh, N0 * DIN);

    // ===== Layer 0: attention scores + softmax =====
    cmb_kernel<<<(DIN * 40 * 32 + 255) / 256, 256, 0, st>>>(W0, as0, ad0, C, DIN);
    tgemm<64><<<tg(N0, 40, 64), 256, 0, st>>>(x, DIN, 0, C, 0, SS, 40, 0, N0, 40, DIN, nullptr, 0);
    alpha_kernel<<<(N1 + 7) / 8, 256, 0, st>>>(rp, perm, es0, SS, a0, den, N1);

    // ===== Layer 0: aggregate (fp16 gather) + fp16 fused (head | skip) GEMM =====
    biasvec_kernel<<<1, HID, 0, st>>>(bsk0, b0, bias);
    aggx_kernel<DIN><<<N1, DIN / 4, 0, st>>>(rp, perm, es0, a0, den, xh, aggX);
    prepack_h<<<(HEADS * ((RREL * DIN + DIN) / 2) * DH + 255) / 256, 256, 0, st>>>(
        W0, Wsk0, BcatP, DIN, DIN);
    hgemm<<<dim3((N1 + 127) / 128, HEADS), 256, HGH_SMEM, st>>>(
        aggX, HEADS * RREL * DIN, (size_t)RREL * DIN,
        xh, DIN,
        BcatP, (size_t)((RREL * DIN + DIN) / 2) * DH,
        out0, HID, (size_t)DH,
        N1, RREL * DIN, DIN, bias);

    // ===== Layer 0: BN + ELU, then out0 -> fp16 =====
    bn_stats<<<64, HID, 0, st>>>(out0, N1, ps, pq);
    bn_final<<<1, HID, 0, st>>>(ps, pq, (float)N1, mu, rstd);
    bn_apply<<<(N1 * HID + 255) / 256, 256, 0, st>>>(out0, N1, g0, be0, mu, rstd, 0);
    f2h_kernel<<<(N1 * HID + 255) / 256, 256, 0, st>>>(out0, oh, N1 * HID);

    // ===== Layer 1: attention + softmax =====
    cmb_kernel<<<(HID * 40 * 32 + 255) / 256, 256, 0, st>>>(W1, as1, ad1, C, HID);
    tgemm<64><<<tg(N1, 40, 64), 256, 0, st>>>(out0, HID, 0, C, 0, SS, 40, 0, N1, 40, HID, nullptr, 0);
    alpha_kernel<<<(N2 + 7) / 8, 256, 0, st>>>(rp + NBINS0, perm, es1, SS, a1,
                                               den + (size_t)NBINS0 * 4, N2);

    // ===== Layer 1: aggregate (fp16 gather) + fp16 fused (head | skip) GEMM =====
    biasvec_kernel<<<1, HID, 0, st>>>(bsk1, b1, bias);
    aggx_kernel<HID><<<N2, HID / 4, 0, st>>>(rp + NBINS0, perm, es1, a1,
                                             den + (size_t)NBINS0 * 4, oh, aggX);
    prepack_h<<<(HEADS * ((RREL * HID + HID) / 2) * DH + 255) / 256, 256, 0, st>>>(
        W1, Wsk1, BcatP, HID, HID);
    hgemm<<<dim3((N2 + 127) / 128, HEADS), 256, HGH_SMEM, st>>>(
        aggX, HEADS * RREL * HID, (size_t)RREL * HID,
        oh, HID,
        BcatP, (size_t)((RREL * HID + HID) / 2) * DH,
        out1, HID, (size_t)DH,
        N2, RREL * HID, HID, bias);

    // ===== Layer 1: BN + ELU =====
    bn_stats<<<64, HID, 0, st>>>(out1, N2, ps, pq);
    bn_final<<<1, HID, 0, st>>>(ps, pq, (float)N2, mu, rstd);
    bn_apply<<<(N2 * HID + 255) / 256, 256, 0, st>>>(out1, N2, g1, be1, mu, rstd, 0);

    // ===== MLP head =====
    tgemm<128><<<tg(N2, HID, 128), 256, 0, st>>>(out1, HID, 0, Wm1, 0, z, HID, 0, N2, HID, HID, bm1, 0);
    bn_stats<<<64, HID, 0, st>>>(z, N2, ps, pq);
    bn_final<<<1, HID, 0, st>>>(ps, pq, (float)N2, mu, rstd);
    bn_apply<<<(N2 * HID + 255) / 256, 256, 0, st>>>(z, N2, gm, bmn, mu, rstd, 1);

    tgemm<64><<<tg(N2, OUTC, 64), 256, 0, st>>>(z, HID, 0, Wm2, 0, out, OUTC, 0, N2, OUTC, HID, bm2, 0);
}

// round 14
// speedup vs baseline: 1.1182x; 1.1182x over previous
#include <cuda_runtime.h>
#include <cuda_fp16.h>
#include <math.h>
#include <stdint.h>

// ---------------- problem constants ----------------
#define N0    120000
#define E0    600000
#define N1    30000
#define E1    150000
#define N2    8000
#define DIN   768
#define HID   512
#define RREL  5
#define HEADS 4
#define DH    128
#define OUTC  153
#define EPSBN 1e-5f

#define NBINS0 (N1 * RREL)
#define NBINS1 (N2 * RREL)
#define NBINSA (NBINS0 + NBINS1)

// ---------------- static scratch ----------------
__device__ __half   g_aggX[(size_t)N1 * HEADS * RREL * DIN];
__device__ uint32_t g_BcatP[(size_t)HEADS * ((RREL * DIN + DIN) / 2) * DH];
__device__ __half   g_xh[(size_t)N0 * DIN];     // x in fp16 (emitted by L0 score GEMM)
__device__ __half   g_oh[(size_t)N1 * HID];     // out0 in fp16 (emitted by L1 score GEMM)
__device__ float g_SS[(size_t)N0 * 40];
__device__ float g_out0[(size_t)N1 * HID];
__device__ float g_out1[(size_t)N2 * HID];
__device__ float g_z[(size_t)N2 * HID];
__device__ float g_alpha0[(size_t)E0 * 4];
__device__ float g_alpha1[(size_t)E1 * 4];
__device__ float g_den[(size_t)NBINSA * 4];
__device__ float g_C[DIN * 40];
__device__ float g_bias[HID];
__device__ float g_ps[64 * HID];
__device__ float g_pq[64 * HID];
__device__ float g_mu[HID];
__device__ float g_rstd[HID];
__device__ int   g_rowptr[NBINSA + 1];
__device__ int   g_perm[E0 + E1];
__device__ int   g_cnt[NBINSA];
__device__ int   g_incl[NBINSA];
__device__ int   g_bsum[1026];

// ---------------- tf32 / fp16 helpers ----------------
__device__ __forceinline__ uint32_t f2tf32(float x) {
    uint32_t u;
    asm("cvt.rna.tf32.f32 %0, %1;" : "=r"(u) : "f"(x));
    return u;
}

__device__ __forceinline__ void mma_tf32(float* d, const uint32_t* a, const uint32_t* b) {
    asm volatile(
        "mma.sync.aligned.m16n8k8.row.col.f32.tf32.tf32.f32 "
        "{%0,%1,%2,%3}, {%4,%5,%6,%7}, {%8,%9}, {%0,%1,%2,%3};\n"
        : "+f"(d[0]), "+f"(d[1]), "+f"(d[2]), "+f"(d[3])
        : "r"(a[0]), "r"(a[1]), "r"(a[2]), "r"(a[3]), "r"(b[0]), "r"(b[1]));
}

__device__ __forceinline__ void mma_f16(float* d, const uint32_t* a, const uint32_t* b) {
    asm volatile(
        "mma.sync.aligned.m16n8k16.row.col.f32.f16.f16.f32 "
        "{%0,%1,%2,%3}, {%4,%5,%6,%7}, {%8,%9}, {%0,%1,%2,%3};\n"
        : "+f"(d[0]), "+f"(d[1]), "+f"(d[2]), "+f"(d[3])
        : "r"(a[0]), "r"(a[1]), "r"(a[2]), "r"(a[3]), "r"(b[0]), "r"(b[1]));
}

// ---------------- merged CSR build ----------------
__global__ void hist2(const int* __restrict__ ed0, const int* __restrict__ et0,
                      const int* __restrict__ ed1, const int* __restrict__ et1,
                      int* __restrict__ cnt) {
    int i = blockIdx.x * blockDim.x + threadIdx.x;
    if (i < E0) {
        atomicAdd(&cnt[ed0[i] * RREL + et0[i]], 1);
    } else if (i < E0 + E1) {
        int e = i - E0;
        atomicAdd(&cnt[NBINS0 + ed1[e] * RREL + et1[e]], 1);
    }
}

__global__ void scan1(const int* __restrict__ cnt, int* __restrict__ incl,
                      int* __restrict__ bsum, int n) {
    __shared__ int sh[256];
    int t = threadIdx.x;
    int i = blockIdx.x * 256 + t;
    int v = (i < n) ? cnt[i] : 0;
    sh[t] = v;
    __syncthreads();
    #pragma unroll
    for (int off = 1; off < 256; off <<= 1) {
        int a = (t >= off) ? sh[t - off] : 0;
        __syncthreads();
        sh[t] += a;
        __syncthreads();
    }
    if (i < n) incl[i] = sh[t];
    if (t == 255) bsum[blockIdx.x] = sh[255];
}

__global__ void scan2(int* __restrict__ bsum, int nb) {
    __shared__ int sh[1024];
    int t = threadIdx.x;
    int v = (t < nb) ? bsum[t] : 0;
    sh[t] = v;
    __syncthreads();
    #pragma unroll
    for (int off = 1; off < 1024; off <<= 1) {
        int a = (t >= off) ? sh[t - off] : 0;
        __syncthreads();
        sh[t] += a;
        __syncthreads();
    }
    if (t < nb) bsum[t] = sh[t] - v;
    if (t == nb - 1) bsum[nb] = sh[t];
}

__global__ void scan3(const int* __restrict__ incl, const int* __restrict__ cnt,
                      const int* __restrict__ bsum, int* __restrict__ rowptr, int n) {
    int i = blockIdx.x * 256 + threadIdx.x;
    if (i < n) rowptr[i] = bsum[i >> 8] + incl[i] - cnt[i];
    if (i == 0) rowptr[n] = bsum[(n + 255) >> 8];
}

__global__ void scatter2(const int* __restrict__ ed0, const int* __restrict__ et0,
                         const int* __restrict__ ed1, const int* __restrict__ et1,
                         const int* __restrict__ rowptr,
                         int* __restrict__ cur, int* __restrict__ perm) {
    int i = blockIdx.x * blockDim.x + threadIdx.x;
    int bin, loc;
    if (i < E0) {
        bin = ed0[i] * RREL + et0[i];
        loc = i;
    } else if (i < E0 + E1) {
        int e = i - E0;
        bin = NBINS0 + ed1[e] * RREL + et1[e];
        loc = e;
    } else return;
    int p = atomicAdd(&cur[bin], 1);
    perm[rowptr[bin] + p] = loc;
}

// ---------------- combined score projection ----------------
__global__ void cmb_kernel(const float* __restrict__ W, const float* __restrict__ as_,
                           const float* __restrict__ ad_, float* __restrict__ C, int K) {
    int gw = (blockIdx.x * blockDim.x + threadIdx.x) >> 5;
    int lane = threadIdx.x & 31;
    if (gw >= K * 40) return;
    int k = gw / 40, col = gw % 40;
    int jh = (col < 20) ? col : col - 20;
    int j = jh / 4, h = jh % 4;
    const float* a = ((col < 20) ? as_ : ad_) + (size_t)(j * 4 + h) * DH;
    const float* w = W + ((size_t)j * K + k) * HID + h * DH;
    float s = 0.f;
    #pragma unroll
    for (int d = lane; d < DH; d += 32) s += w[d] * a[d];
    for (int off = 16; off; off >>= 1) s += __shfl_xor_sync(0xffffffffu, s, off);
    if (lane == 0) C[k * 40 + col] = s;
}

__global__ void biasvec_kernel(const float* __restrict__ bsk, const float* __restrict__ b,
                               float* __restrict__ out) {
    int t = threadIdx.x;
    float s = bsk[t];
    for (int j = 0; j < RREL; j++) s += b[j * HID + t];
    out[t] = s;
}

// pack per head, k-pair layout
__global__ void prepack_h(const float* __restrict__ W, const float* __restrict__ Wsk,
                          uint32_t* __restrict__ Bp, int K, int KX) {
    int idx = blockIdx.x * blockDim.x + threadIdx.x;
    int kt2 = (RREL * K + KX) / 2;
    int total = HEADS * kt2 * DH;
    if (idx >= total) return;
    int n = idx & (DH - 1);
    int rest = idx >> 7;
    int kp = rest % kt2;
    int h = rest / kt2;
    float v[2];
    #pragma unroll
    for (int q = 0; q < 2; q++) {
        int k = 2 * kp + q;
        if (k < RREL * K) {
            int j = k / K, kk = k % K;
            v[q] = W[((size_t)j * K + kk) * HID + h * DH + n];
        } else {
            v[q] = Wsk[(size_t)(k - RREL * K) * HID + h * DH + n];
        }
    }
    __half2 p = __halves2half2(__float2half_rn(v[0]), __float2half_rn(v[1]));
    Bp[idx] = *(uint32_t*)&p;
}

// ---------------- mma.sync tf32 GEMM (optionally emits fp16 copy of A) ----------------
// Ah != nullptr requires grid.x == 1 && grid.z == 1 (each A element fetched exactly once).
template <int BN>
__global__ void __launch_bounds__(256, 2) tgemm(
    const float* __restrict__ A, int lda, size_t hsA,
    const float* __restrict__ B, size_t hsB,
    float* __restrict__ C, int ldc, size_t hsC,
    int M, int N, int K, const float* __restrict__ bias, int accum,
    __half* __restrict__ Ah) {
    constexpr int MF  = (BN == 128) ? 4 : 2;
    constexpr int NQ  = BN / 4;
    constexpr int ITB = BN / 64;
    __shared__ uint32_t As[2][16 * 128];
    __shared__ uint32_t Bs[2][16 * BN];
    A += (size_t)blockIdx.z * hsA;
    B += (size_t)blockIdx.z * hsB;
    C += (size_t)blockIdx.z * hsC;
    const int bm = blockIdx.y * 128, bn = blockIdx.x * BN;
    const int tid = threadIdx.x;
    const int lane = tid & 31, warp = tid >> 5;
    const int wm = (BN == 128) ? (warp >> 2) * 64 : (warp >> 1) * 32;
    const int wn = (BN == 128) ? (warp & 3) * 32 : (warp & 1) * 32;
    const int g = lane >> 2, ctg = lane & 3;
    const bool n_vec = ((N & 3) == 0);

    float acc[MF][4][4];
    #pragma unroll
    for (int mf = 0; mf < MF; mf++)
        #pragma unroll
        for (int nf = 0; nf < 4; nf++)
            #pragma unroll
            for (int q = 0; q < 4; q++) acc[mf][nf][q] = 0.f;

    float4 aReg[2];
    float  bReg[ITB][4];

    auto fetch = [&](int k0) {
        #pragma unroll
        for (int it = 0; it < 2; it++) {
            int idx = tid + it * 256;
            int r = idx >> 2, c4 = idx & 3;
            int gr = bm + r;
            aReg[it] = make_float4(0.f, 0.f, 0.f, 0.f);
            if (gr < M) {
                aReg[it] = *(const float4*)(A + (size_t)gr * lda + k0 + c4 * 4);
                if (Ah) {
                    __half2 p0 = __halves2half2(__float2half_rn(aReg[it].x),
                                                __float2half_rn(aReg[it].y));
                    __half2 p1 = __halves2half2(__float2half_rn(aReg[it].z),
                                                __float2half_rn(aReg[it].w));
                    *(uint2*)(Ah + (size_t)gr * lda + k0 + c4 * 4) =
                        make_uint2(*(uint32_t*)&p0, *(uint32_t*)&p1);
                }
            }
        }
        #pragma unroll
        for (int it = 0; it < ITB; it++) {
            int idx = tid + it * 256;
            int kk = idx / NQ, nq = idx % NQ;
            int gn = bn + nq * 4;
            const float* bp = B + (size_t)(k0 + kk) * N + gn;
            bReg[it][0] = bReg[it][1] = bReg[it][2] = bReg[it][3] = 0.f;
            if (n_vec && gn + 3 < N) {
                float4 v = *(const float4*)bp;
                bReg[it][0] = v.x; bReg[it][1] = v.y; bReg[it][2] = v.z; bReg[it][3] = v.w;
            } else {
                if (gn < N)     bReg[it][0] = bp[0];
                if (gn + 1 < N) bReg[it][1] = bp[1];
                if (gn + 2 < N) bReg[it][2] = bp[2];
                if (gn + 3 < N) bReg[it][3] = bp[3];
            }
        }
    };

    auto stage = [&](int buf) {
        #pragma unroll
        for (int it = 0; it < 2; it++) {
            int idx = tid + it * 256;
            int r = idx >> 2, c4 = idx & 3;
            uint32_t uv[4] = {f2tf32(aReg[it].x), f2tf32(aReg[it].y),
                              f2tf32(aReg[it].z), f2tf32(aReg[it].w)};
            #pragma unroll
            for (int s = 0; s < 4; s++) {
                int i = (s + lane) & 3;
                int kk = c4 * 4 + i;
                As[buf][kk * 128 + (r ^ (8 * (kk & 3)))] = uv[i];
            }
        }
        #pragma unroll
        for (int it = 0; it < ITB; it++) {
            int idx = tid + it * 256;
            int kk = idx / NQ, nq = idx % NQ;
            *(uint4*)&Bs[buf][kk * BN + ((nq * 4) ^ (8 * (kk & 3)))] =
                make_uint4(f2tf32(bReg[it][0]), f2tf32(bReg[it][1]),
                           f2tf32(bReg[it][2]), f2tf32(bReg[it][3]));
        }
    };

    const int nk = K >> 4;
    fetch(0);
    stage(0);
    if (nk > 1) fetch(16);
    __syncthreads();

    for (int ki = 0; ki < nk; ki++) {
        const int cur = ki & 1;
        if (ki + 1 < nk) {
            stage(cur ^ 1);
            if (ki + 2 < nk) fetch((ki + 2) << 4);
        }

        #pragma unroll
        for (int ks = 0; ks < 16; ks += 8) {
            uint32_t af[MF][4], bf[4][2];
            int kA0 = ks + ctg;
            int kA1 = ks + 4 + ctg;
            #pragma unroll
            for (int mf = 0; mf < MF; mf++) {
                int row = wm + mf * 16 + g;
                af[mf][0] = As[cur][kA0 * 128 + (row ^ (8 * ctg))];
                af[mf][1] = As[cur][kA0 * 128 + ((row + 8) ^ (8 * ctg))];
                af[mf][2] = As[cur][kA1 * 128 + (row ^ (8 * ctg))];
                af[mf][3] = As[cur][kA1 * 128 + ((row + 8) ^ (8 * ctg))];
            }
            #pragma unroll
            for (int nf = 0; nf < 4; nf++) {
                int col = wn + nf * 8 + g;
                bf[nf][0] = Bs[cur][kA0 * BN + (col ^ (8 * ctg))];
                bf[nf][1] = Bs[cur][kA1 * BN + (col ^ (8 * ctg))];
            }
            #pragma unroll
            for (int mf = 0; mf < MF; mf++)
                #pragma unroll
                for (int nf = 0; nf < 4; nf++)
                    mma_tf32(acc[mf][nf], af[mf], bf[nf]);
        }
        __syncthreads();
    }

    #pragma unroll
    for (int mf = 0; mf < MF; mf++) {
        #pragma unroll
        for (int half = 0; half < 2; half++) {
            int r = bm + wm + mf * 16 + g + half * 8;
            if (r >= M) continue;
            #pragma unroll
            for (int nf = 0; nf < 4; nf++) {
                int c = bn + wn + nf * 8 + ctg * 2;
                float v0 = acc[mf][nf][half * 2 + 0];
                float v1 = acc[mf][nf][half * 2 + 1];
                if (c < N) {
                    float base0 = accum ? C[(size_t)r * ldc + c] : 0.f;
                    C[(size_t)r * ldc + c] = base0 + v0 + (bias ? bias[c] : 0.f);
                }
                if (c + 1 < N) {
                    float base1 = accum ? C[(size_t)r * ldc + c + 1] : 0.f;
                    C[(size_t)r * ldc + c + 1] = base1 + v1 + (bias ? bias[c + 1] : 0.f);
                }
            }
        }
    }
}

// ---------------- fp16 cp.async head GEMM, BK=64, fused skip ----------------
#define ASH 36
#define BSH 136
#define HGH_SMEM (2 * (128 * ASH + 32 * BSH) * 4)

__global__ void __launch_bounds__(256, 2) hgemm(
    const __half* __restrict__ A1, int lda1, size_t hsA1,
    const __half* __restrict__ A2, int lda2,
    const uint32_t* __restrict__ Bp, size_t hsB,
    float* __restrict__ C, int ldc, size_t hsC,
    int M, int KA, int KX, const float* __restrict__ bias) {
    extern __shared__ uint32_t smu[];
    uint32_t* Asm[2] = {smu, smu + 128 * ASH};
    uint32_t* Bsm[2] = {smu + 2 * 128 * ASH, smu + 2 * 128 * ASH + 32 * BSH};
    A1 += (size_t)blockIdx.y * hsA1;
    Bp += (size_t)blockIdx.y * hsB;
    C  += (size_t)blockIdx.y * hsC;
    bias += (size_t)blockIdx.y * DH;
    const int bm = blockIdx.x * 128;
    const int tid = threadIdx.x, lane = tid & 31, warp = tid >> 5;
    const int wm = (warp >> 2) * 64, wn = (warp & 3) * 32;
    const int g = lane >> 2, ctg = lane & 3;

    float acc[4][4][4];
    #pragma unroll
    for (int mf = 0; mf < 4; mf++)
        #pragma unroll
        for (int nf = 0; nf < 4; nf++)
            #pragma unroll
            for (int q = 0; q < 4; q++) acc[mf][nf][q] = 0.f;

    auto issue = [&](int buf, int k0) {
        const __half* Ab;
        int ldx, kc;
        if (k0 < KA) { Ab = A1; ldx = lda1; kc = k0; }
        else         { Ab = A2; ldx = lda2; kc = k0 - KA; }
        #pragma unroll
        for (int it = 0; it < 4; it++) {
            int idx = tid + it * 256;
            int r = idx >> 3, c8 = idx & 7;
            const __half* src = Ab + (size_t)(bm + r) * ldx + kc + c8 * 8;
            uint32_t dst = (uint32_t)__cvta_generic_to_shared(&Asm[buf][r * ASH + c8 * 4]);
            int sz = (bm + r < M) ? 16 : 0;
            asm volatile("cp.async.cg.shared.global [%0], [%1], 16, %2;"
                         :: "r"(dst), "l"(src), "r"(sz));
        }
        int kp0 = k0 >> 1;
        #pragma unroll
        for (int it = 0; it < 4; it++) {
            int idx = tid + it * 256;
            int kp = idx >> 5, nq = idx & 31;
            const uint32_t* src = Bp + (size_t)(kp0 + kp) * 128 + nq * 4;
            uint32_t dst = (uint32_t)__cvta_generic_to_shared(&Bsm[buf][kp * BSH + nq * 4]);
            asm volatile("cp.async.cg.shared.global [%0], [%1], 16;" :: "r"(dst), "l"(src));
        }
        asm volatile("cp.async.commit_group;");
    };

    const int nk = (KA + KX) >> 6;
    issue(0, 0);
    issue(1, 64);
    asm volatile("cp.async.wait_group 1;");
    __syncthreads();

    for (int ki = 0; ki < nk; ki++) {
        const int cur = ki & 1;
        const uint32_t* Ab = Asm[cur];
        const uint32_t* Bb = Bsm[cur];

        #pragma unroll
        for (int kc2 = 0; kc2 < 4; kc2++) {
            int kb = kc2 * 8;
            uint32_t af[4][4], bf[4][2];
            #pragma unroll
            for (int mf = 0; mf < 4; mf++) {
                int row = wm + mf * 16 + g;
                af[mf][0] = Ab[row * ASH + kb + ctg];
                af[mf][1] = Ab[(row + 8) * ASH + kb + ctg];
                af[mf][2] = Ab[row * ASH + kb + 4 + ctg];
                af[mf][3] = Ab[(row + 8) * ASH + kb + 4 + ctg];
            }
            #pragma unroll
            for (int nf = 0; nf < 4; nf++) {
                int col = wn + nf * 8 + g;
                bf[nf][0] = Bb[(kb + ctg) * BSH + col];
                bf[nf][1] = Bb[(kb + 4 + ctg) * BSH + col];
            }
            #pragma unroll
            for (int mf = 0; mf < 4; mf++)
                #pragma unroll
                for (int nf = 0; nf < 4; nf++)
                    mma_f16(acc[mf][nf], af[mf], bf[nf]);
        }

        __syncthreads();
        if (ki + 2 < nk) issue(cur, (ki + 2) << 6);
        if (ki + 1 < nk) {
            if (ki + 2 < nk) asm volatile("cp.async.wait_group 1;");
            else             asm volatile("cp.async.wait_group 0;");
            __syncthreads();
        }
    }

    #pragma unroll
    for (int mf = 0; mf < 4; mf++) {
        #pragma unroll
        for (int half = 0; half < 2; half++) {
            int r = bm + wm + mf * 16 + g + half * 8;
            if (r >= M) continue;
            float* cr = C + (size_t)r * ldc;
            #pragma unroll
            for (int nf = 0; nf < 4; nf++) {
                int c = wn + nf * 8 + ctg * 2;
                cr[c]     = acc[mf][nf][half * 2 + 0] + bias[c];
                cr[c + 1] = acc[mf][nf][half * 2 + 1] + bias[c + 1];
            }
        }
    }
}

// ---------------- single-pass unnormalized softmax ----------------
__global__ void alpha_kernel(const int* __restrict__ rowptr, const int* __restrict__ perm,
                             const int* __restrict__ esrc,
                             const float* __restrict__ SS, float* __restrict__ alpha,
                             float* __restrict__ den, int ndst) {
    int d = blockIdx.x * 8 + (threadIdx.x >> 5);
    if (d >= ndst) return;
    int lane = threadIdx.x & 31;
    for (int j = 0; j < RREL; j++) {
        int bin = d * RREL + j;
        int beg = rowptr[bin], end = rowptr[bin + 1];
        float sd[4];
        #pragma unroll
        for (int h = 0; h < 4; h++) sd[h] = SS[(size_t)d * 40 + 20 + j * 4 + h];

        float sm[4] = {0.f, 0.f, 0.f, 0.f};
        for (int i = beg + lane; i < end; i += 32) {
            int e = perm[i];
            int s = esrc[e];
            float ex[4];
            #pragma unroll
            for (int h = 0; h < 4; h++) {
                float sc = SS[(size_t)s * 40 + j * 4 + h] + sd[h];
                sc = sc > 0.f ? sc : 0.2f * sc;
                ex[h] = expf(sc);
                sm[h] += ex[h];
            }
            *(float4*)(alpha + (size_t)e * 4) = make_float4(ex[0], ex[1], ex[2], ex[3]);
        }
        #pragma unroll
        for (int h = 0; h < 4; h++)
            for (int off = 16; off; off >>= 1)
                sm[h] += __shfl_xor_sync(0xffffffffu, sm[h], off);
        if (lane == 0)
            *(float4*)(den + (size_t)bin * 4) = make_float4(sm[0], sm[1], sm[2], sm[3]);
    }
}

// ---------------- aggregate: fp16 gather, fused 1/denom, half2 stores ----------------
template <int DIN_>
__global__ void __launch_bounds__(DIN_ / 4) aggx_kernel(
    const int* __restrict__ rowptr, const int* __restrict__ perm,
    const int* __restrict__ esrc,
    const float* __restrict__ alpha, const float* __restrict__ den,
    const __half* __restrict__ Xh, __half* __restrict__ aggX) {
    int d = blockIdx.x, t = threadIdx.x;   // t < DIN_/4
    #pragma unroll
    for (int j = 0; j < RREL; j++) {
        int bin = d * RREL + j;
        float acc[HEADS][4];
        #pragma unroll
        for (int h = 0; h < HEADS; h++)
            #pragma unroll
            for (int c = 0; c < 4; c++) acc[h][c] = 0.f;

        int beg = rowptr[bin], end = rowptr[bin + 1];
        for (int i = beg; i < end; i++) {
            int e = perm[i];
            int s = esrc[e];
            float4 al = *(const float4*)(alpha + (size_t)e * 4);
            uint2 pk = *(const uint2*)(Xh + (size_t)s * DIN_ + t * 4);
            float2 f0 = __half22float2(*(__half2*)&pk.x);
            float2 f1 = __half22float2(*(__half2*)&pk.y);
            float xv0 = f0.x, xv1 = f0.y, xv2 = f1.x, xv3 = f1.y;
            acc[0][0] += al.x * xv0; acc[0][1] += al.x * xv1;
            acc[0][2] += al.x * xv2; acc[0][3] += al.x * xv3;
            acc[1][0] += al.y * xv0; acc[1][1] += al.y * xv1;
            acc[1][2] += al.y * xv2; acc[1][3] += al.y * xv3;
            acc[2][0] += al.z * xv0; acc[2][1] += al.z * xv1;
            acc[2][2] += al.z * xv2; acc[2][3] += al.z * xv3;
            acc[3][0] += al.w * xv0; acc[3][1] += al.w * xv1;
            acc[3][2] += al.w * xv2; acc[3][3] += al.w * xv3;
        }
        float4 dn = *(const float4*)(den + (size_t)bin * 4);
        float rs[4] = {1.f / fmaxf(dn.x, 1e-16f), 1.f / fmaxf(dn.y, 1e-16f),
                       1.f / fmaxf(dn.z, 1e-16f), 1.f / fmaxf(dn.w, 1e-16f)};
        #pragma unroll
        for (int h = 0; h < HEADS; h++) {
            __half2 p0 = __halves2half2(__float2half_rn(acc[h][0] * rs[h]),
                                        __float2half_rn(acc[h][1] * rs[h]));
            __half2 p1 = __halves2half2(__float2half_rn(acc[h][2] * rs[h]),
                                        __float2half_rn(acc[h][3] * rs[h]));
            uint2 pk = make_uint2(*(uint32_t*)&p0, *(uint32_t*)&p1);
            *(uint2*)(aggX + ((size_t)(d * 4 + h)) * (RREL * DIN_) + j * DIN_ + t * 4) = pk;
        }
    }
}

// ---------------- batch-norm (partial-sum slab) ----------------
__global__ void bn_stats(const float* __restrict__ X, int n,
                         float* __restrict__ ps, float* __restrict__ pq) {
    int t = threadIdx.x;
    int rpb = (n + gridDim.x - 1) / gridDim.x;
    int r0 = blockIdx.x * rpb;
    int r1 = min(n, r0 + rpb);
    float s = 0.f, q = 0.f;
    for (int r = r0; r < r1; r++) {
        float v = X[(size_t)r * HID + t];
        s += v;
        q += v * v;
    }
    ps[blockIdx.x * HID + t] = s;
    pq[blockIdx.x * HID + t] = q;
}

__global__ void bn_final(const float* __restrict__ ps, const float* __restrict__ pq,
                         float n, float* __restrict__ mu, float* __restrict__ rstd) {
    int t = threadIdx.x;
    float s = 0.f, q = 0.f;
    #pragma unroll 8
    for (int b = 0; b < 64; b++) {
        s += ps[b * HID + t];
        q += pq[b * HID + t];
    }
    float m = s / n;
    float v = q / n - m * m;
    mu[t] = m;
    rstd[t] = rsqrtf(v + EPSBN);
}

__global__ void bn_apply(float* __restrict__ X, int n,
                         const float* __restrict__ g, const float* __restrict__ be,
                         const float* __restrict__ mu, const float* __restrict__ rstd, int act) {
    int idx = blockIdx.x * blockDim.x + threadIdx.x;
    int total = n * HID;
    if (idx >= total) return;
    int c = idx & (HID - 1);
    float v = X[idx];
    float y = g[c] * ((v - mu[c]) * rstd[c]) + be[c];
    X[idx] = (act == 0) ? (y > 0.f ? y : expm1f(y)) : fmaxf(y, 0.f);
}

// ---------------- host orchestration ----------------
static inline dim3 tg(int M, int N, int BN_, int Z = 1) {
    return dim3((N + BN_ - 1) / BN_, (M + 127) / 128, Z);
}

extern "C" void kernel_launch(void* const* d_in, const int* in_sizes, int n_in,
                              void* d_out, int out_size) {
    const float* x    = (const float*)d_in[0];
    const int*   es0  = (const int*)d_in[1];
    const int*   ed0  = (const int*)d_in[2];
    const int*   et0  = (const int*)d_in[3];
    const int*   es1  = (const int*)d_in[4];
    const int*   ed1  = (const int*)d_in[5];
    const int*   et1  = (const int*)d_in[6];
    const float* W0   = (const float*)d_in[7];
    const float* as0  = (const float*)d_in[8];
    const float* ad0  = (const float*)d_in[9];
    const float* b0   = (const float*)d_in[10];
    const float* Wsk0 = (const float*)d_in[11];
    const float* bsk0 = (const float*)d_in[12];
    const float* g0   = (const float*)d_in[13];
    const float* be0  = (const float*)d_in[14];
    const float* W1   = (const float*)d_in[15];
    const float* as1  = (const float*)d_in[16];
    const float* ad1  = (const float*)d_in[17];
    const float* b1   = (const float*)d_in[18];
    const float* Wsk1 = (const float*)d_in[19];
    const float* bsk1 = (const float*)d_in[20];
    const float* g1   = (const float*)d_in[21];
    const float* be1  = (const float*)d_in[22];
    const float* Wm1  = (const float*)d_in[23];
    const float* bm1  = (const float*)d_in[24];
    const float* gm   = (const float*)d_in[25];
    const float* bmn  = (const float*)d_in[26];
    const float* Wm2  = (const float*)d_in[27];
    const float* bm2  = (const float*)d_in[28];
    float* out = (float*)d_out;

    void *pAgg, *pBcP, *pXh, *pOh, *pSS, *pOut0, *pOut1, *pZ, *pA0, *pA1, *pDen, *pC, *pBias;
    void *pPS, *pPQ, *pMu, *pRs, *pRp, *pPerm, *pCnt, *pIncl, *pBsum;
    cudaGetSymbolAddress(&pAgg, g_aggX);
    cudaGetSymbolAddress(&pBcP, g_BcatP);
    cudaGetSymbolAddress(&pXh, g_xh);
    cudaGetSymbolAddress(&pOh, g_oh);
    cudaGetSymbolAddress(&pSS, g_SS);
    cudaGetSymbolAddress(&pOut0, g_out0);
    cudaGetSymbolAddress(&pOut1, g_out1);
    cudaGetSymbolAddress(&pZ, g_z);
    cudaGetSymbolAddress(&pA0, g_alpha0);
    cudaGetSymbolAddress(&pA1, g_alpha1);
    cudaGetSymbolAddress(&pDen, g_den);
    cudaGetSymbolAddress(&pC, g_C);
    cudaGetSymbolAddress(&pBias, g_bias);
    cudaGetSymbolAddress(&pPS, g_ps);
    cudaGetSymbolAddress(&pPQ, g_pq);
    cudaGetSymbolAddress(&pMu, g_mu);
    cudaGetSymbolAddress(&pRs, g_rstd);
    cudaGetSymbolAddress(&pRp, g_rowptr);
    cudaGetSymbolAddress(&pPerm, g_perm);
    cudaGetSymbolAddress(&pCnt, g_cnt);
    cudaGetSymbolAddress(&pIncl, g_incl);
    cudaGetSymbolAddress(&pBsum, g_bsum);

    __half* aggX    = (__half*)pAgg;
    uint32_t* BcatP = (uint32_t*)pBcP;
    __half* xh      = (__half*)pXh;
    __half* oh      = (__half*)pOh;
    float* SS   = (float*)pSS;
    float* out0 = (float*)pOut0;
    float* out1 = (float*)pOut1;
    float* z    = (float*)pZ;
    float* a0   = (float*)pA0;
    float* a1   = (float*)pA1;
    float* den  = (float*)pDen;
    float* C    = (float*)pC;
    float* bias = (float*)pBias;
    float* ps   = (float*)pPS;
    float* pq   = (float*)pPQ;
    float* mu   = (float*)pMu;
    float* rstd = (float*)pRs;
    int* rp     = (int*)pRp;
    int* perm   = (int*)pPerm;
    int* cnt    = (int*)pCnt;
    int* incl   = (int*)pIncl;
    int* bsum   = (int*)pBsum;

    cudaStream_t st = 0;
    const int NBA = (NBINSA + 255) / 256;
    const int EA  = E0 + E1;

    cudaFuncSetAttribute(hgemm, cudaFuncAttributeMaxDynamicSharedMemorySize, HGH_SMEM);

    // ===== merged CSR (both layers) =====
    cudaMemsetAsync(cnt, 0, NBINSA * sizeof(int), st);
    hist2<<<(EA + 255) / 256, 256, 0, st>>>(ed0, et0, ed1, et1, cnt);
    scan1<<<NBA, 256, 0, st>>>(cnt, incl, bsum, NBINSA);
    scan2<<<1, 1024, 0, st>>>(bsum, NBA);
    scan3<<<NBA, 256, 0, st>>>(incl, cnt, bsum, rp, NBINSA);
    cudaMemsetAsync(cnt, 0, NBINSA * sizeof(int), st);
    scatter2<<<(EA + 255) / 256, 256, 0, st>>>(ed0, et0, ed1, et1, rp, cnt, perm);

    // ===== Layer 0: attention scores (emits xh) + softmax =====
    cmb_kernel<<<(DIN * 40 * 32 + 255) / 256, 256, 0, st>>>(W0, as0, ad0, C, DIN);
    tgemm<64><<<tg(N0, 40, 64), 256, 0, st>>>(x, DIN, 0, C, 0, SS, 40, 0, N0, 40, DIN,
                                              nullptr, 0, xh);
    alpha_kernel<<<(N1 + 7) / 8, 256, 0, st>>>(rp, perm, es0, SS, a0, den, N1);

    // ===== Layer 0: aggregate (fp16 gather) + fp16 fused (head | skip) GEMM =====
    biasvec_kernel<<<1, HID, 0, st>>>(bsk0, b0, bias);
    aggx_kernel<DIN><<<N1, DIN / 4, 0, st>>>(rp, perm, es0, a0, den, xh, aggX);
    prepack_h<<<(HEADS * ((RREL * DIN + DIN) / 2) * DH + 255) / 256, 256, 0, st>>>(
        W0, Wsk0, BcatP, DIN, DIN);
    hgemm<<<dim3((N1 + 127) / 128, HEADS), 256, HGH_SMEM, st>>>(
        aggX, HEADS * RREL * DIN, (size_t)RREL * DIN,
        xh, DIN,
        BcatP, (size_t)((RREL * DIN + DIN) / 2) * DH,
        out0, HID, (size_t)DH,
        N1, RREL * DIN, DIN, bias);

    // ===== Layer 0: BN + ELU =====
    bn_stats<<<64, HID, 0, st>>>(out0, N1, ps, pq);
    bn_final<<<1, HID, 0, st>>>(ps, pq, (float)N1, mu, rstd);
    bn_apply<<<(N1 * HID + 255) / 256, 256, 0, st>>>(out0, N1, g0, be0, mu, rstd, 0);

    // ===== Layer 1: attention scores (emits oh) + softmax =====
    cmb_kernel<<<(HID * 40 * 32 + 255) / 256, 256, 0, st>>>(W1, as1, ad1, C, HID);
    tgemm<64><<<tg(N1, 40, 64), 256, 0, st>>>(out0, HID, 0, C, 0, SS, 40, 0, N1, 40, HID,
                                              nullptr, 0, oh);
    alpha_kernel<<<(N2 + 7) / 8, 256, 0, st>>>(rp + NBINS0, perm, es1, SS, a1,
                                               den + (size_t)NBINS0 * 4, N2);

    // ===== Layer 1: aggregate (fp16 gather) + fp16 fused (head | skip) GEMM =====
    biasvec_kernel<<<1, HID, 0, st>>>(bsk1, b1, bias);
    aggx_kernel<HID><<<N2, HID / 4, 0, st>>>(rp + NBINS0, perm, es1, a1,
                                             den + (size_t)NBINS0 * 4, oh, aggX);
    prepack_h<<<(HEADS * ((RREL * HID + HID) / 2) * DH + 255) / 256, 256, 0, st>>>(
        W1, Wsk1, BcatP, HID, HID);
    hgemm<<<dim3((N2 + 127) / 128, HEADS), 256, HGH_SMEM, st>>>(
        aggX, HEADS * RREL * HID, (size_t)RREL * HID,
        oh, HID,
        BcatP, (size_t)((RREL * HID + HID) / 2) * DH,
        out1, HID, (size_t)DH,
        N2, RREL * HID, HID, bias);

    // ===== Layer 1: BN + ELU =====
    bn_stats<<<64, HID, 0, st>>>(out1, N2, ps, pq);
    bn_final<<<1, HID, 0, st>>>(ps, pq, (float)N2, mu, rstd);
    bn_apply<<<(N2 * HID + 255) / 256, 256, 0, st>>>(out1, N2, g1, be1, mu, rstd, 0);

    // ===== MLP head =====
    tgemm<128><<<tg(N2, HID, 128), 256, 0, st>>>(out1, HID, 0, Wm1, 0, z, HID, 0, N2, HID, HID,
                                                 bm1, 0, nullptr);
    bn_stats<<<64, HID, 0, st>>>(z, N2, ps, pq);
    bn_final<<<1, HID, 0, st>>>(ps, pq, (float)N2, mu, rstd);
    bn_apply<<<(N2 * HID + 255) / 256, 256, 0, st>>>(z, N2, gm, bmn, mu, rstd, 1);

    tgemm<64><<<tg(N2, OUTC, 64), 256, 0, st>>>(z, HID, 0, Wm2, 0, out, OUTC, 0, N2, OUTC, HID,
                                                bm2, 0, nullptr);
}

// round 15
// speedup vs baseline: 1.1825x; 1.0575x over previous
#include <cuda_runtime.h>
#include <cuda_fp16.h>
#include <math.h>
#include <stdint.h>

// ---------------- problem constants ----------------
#define N0    120000
#define E0    600000
#define N1    30000
#define E1    150000
#define N2    8000
#define DIN   768
#define HID   512
#define RREL  5
#define HEADS 4
#define DH    128
#define OUTC  153
#define EPSBN 1e-5f

#define NBINS0 (N1 * RREL)
#define NBINS1 (N2 * RREL)
#define NBINSA (NBINS0 + NBINS1)
#define EA_ALL (E0 + E1)

// ---------------- static scratch ----------------
__device__ __half   g_aggX[(size_t)N1 * HEADS * RREL * DIN];
__device__ uint32_t g_BcatP[(size_t)HEADS * ((RREL * DIN + DIN) / 2) * DH];
__device__ __half   g_xh[(size_t)N0 * DIN];     // x in fp16 (emitted by L0 score GEMM)
__device__ __half   g_oh[(size_t)N1 * HID];     // out0 in fp16 (emitted by L1 score GEMM)
__device__ float g_SS[(size_t)N0 * 40];
__device__ float g_out0[(size_t)N1 * HID];
__device__ float g_out1[(size_t)N2 * HID];
__device__ float g_z[(size_t)N2 * HID];
__device__ float g_alphas[(size_t)EA_ALL * 4];  // CSR-sorted unnormalized exp
__device__ int   g_esort[EA_ALL];               // CSR-sorted source index
__device__ float g_den[(size_t)NBINSA * 4];
__device__ float g_C[DIN * 40];
__device__ float g_bias[HID];
__device__ float g_ps[64 * HID];
__device__ float g_pq[64 * HID];
__device__ float g_mu[HID];
__device__ float g_rstd[HID];
__device__ int   g_rowptr[NBINSA + 1];
__device__ int   g_perm[EA_ALL];
__device__ int   g_cnt[NBINSA];
__device__ int   g_incl[NBINSA];
__device__ int   g_bsum[1026];

// ---------------- tf32 / fp16 helpers ----------------
__device__ __forceinline__ uint32_t f2tf32(float x) {
    uint32_t u;
    asm("cvt.rna.tf32.f32 %0, %1;" : "=r"(u) : "f"(x));
    return u;
}

__device__ __forceinline__ void mma_tf32(float* d, const uint32_t* a, const uint32_t* b) {
    asm volatile(
        "mma.sync.aligned.m16n8k8.row.col.f32.tf32.tf32.f32 "
        "{%0,%1,%2,%3}, {%4,%5,%6,%7}, {%8,%9}, {%0,%1,%2,%3};\n"
        : "+f"(d[0]), "+f"(d[1]), "+f"(d[2]), "+f"(d[3])
        : "r"(a[0]), "r"(a[1]), "r"(a[2]), "r"(a[3]), "r"(b[0]), "r"(b[1]));
}

__device__ __forceinline__ void mma_f16(float* d, const uint32_t* a, const uint32_t* b) {
    asm volatile(
        "mma.sync.aligned.m16n8k16.row.col.f32.f16.f16.f32 "
        "{%0,%1,%2,%3}, {%4,%5,%6,%7}, {%8,%9}, {%0,%1,%2,%3};\n"
        : "+f"(d[0]), "+f"(d[1]), "+f"(d[2]), "+f"(d[3])
        : "r"(a[0]), "r"(a[1]), "r"(a[2]), "r"(a[3]), "r"(b[0]), "r"(b[1]));
}

// ---------------- merged CSR build ----------------
__global__ void hist2(const int* __restrict__ ed0, const int* __restrict__ et0,
                      const int* __restrict__ ed1, const int* __restrict__ et1,
                      int* __restrict__ cnt) {
    int i = blockIdx.x * blockDim.x + threadIdx.x;
    if (i < E0) {
        atomicAdd(&cnt[ed0[i] * RREL + et0[i]], 1);
    } else if (i < EA_ALL) {
        int e = i - E0;
        atomicAdd(&cnt[NBINS0 + ed1[e] * RREL + et1[e]], 1);
    }
}

__global__ void scan1(const int* __restrict__ cnt, int* __restrict__ incl,
                      int* __restrict__ bsum, int n) {
    __shared__ int sh[256];
    int t = threadIdx.x;
    int i = blockIdx.x * 256 + t;
    int v = (i < n) ? cnt[i] : 0;
    sh[t] = v;
    __syncthreads();
    #pragma unroll
    for (int off = 1; off < 256; off <<= 1) {
        int a = (t >= off) ? sh[t - off] : 0;
        __syncthreads();
        sh[t] += a;
        __syncthreads();
    }
    if (i < n) incl[i] = sh[t];
    if (t == 255) bsum[blockIdx.x] = sh[255];
}

__global__ void scan2(int* __restrict__ bsum, int nb) {
    __shared__ int sh[1024];
    int t = threadIdx.x;
    int v = (t < nb) ? bsum[t] : 0;
    sh[t] = v;
    __syncthreads();
    #pragma unroll
    for (int off = 1; off < 1024; off <<= 1) {
        int a = (t >= off) ? sh[t - off] : 0;
        __syncthreads();
        sh[t] += a;
        __syncthreads();
    }
    if (t < nb) bsum[t] = sh[t] - v;
    if (t == nb - 1) bsum[nb] = sh[t];
}

__global__ void scan3(const int* __restrict__ incl, const int* __restrict__ cnt,
                      const int* __restrict__ bsum, int* __restrict__ rowptr, int n) {
    int i = blockIdx.x * 256 + threadIdx.x;
    if (i < n) rowptr[i] = bsum[i >> 8] + incl[i] - cnt[i];
    if (i == 0) rowptr[n] = bsum[(n + 255) >> 8];
}

__global__ void scatter2(const int* __restrict__ ed0, const int* __restrict__ et0,
                         const int* __restrict__ ed1, const int* __restrict__ et1,
                         const int* __restrict__ rowptr,
                         int* __restrict__ cur, int* __restrict__ perm) {
    int i = blockIdx.x * blockDim.x + threadIdx.x;
    int bin, loc;
    if (i < E0) {
        bin = ed0[i] * RREL + et0[i];
        loc = i;
    } else if (i < EA_ALL) {
        int e = i - E0;
        bin = NBINS0 + ed1[e] * RREL + et1[e];
        loc = e;
    } else return;
    int p = atomicAdd(&cur[bin], 1);
    perm[rowptr[bin] + p] = loc;
}

// ---------------- combined score projection ----------------
__global__ void cmb_kernel(const float* __restrict__ W, const float* __restrict__ as_,
                           const float* __restrict__ ad_, float* __restrict__ C, int K) {
    int gw = (blockIdx.x * blockDim.x + threadIdx.x) >> 5;
    int lane = threadIdx.x & 31;
    if (gw >= K * 40) return;
    int k = gw / 40, col = gw % 40;
    int jh = (col < 20) ? col : col - 20;
    int j = jh / 4, h = jh % 4;
    const float* a = ((col < 20) ? as_ : ad_) + (size_t)(j * 4 + h) * DH;
    const float* w = W + ((size_t)j * K + k) * HID + h * DH;
    float s = 0.f;
    #pragma unroll
    for (int d = lane; d < DH; d += 32) s += w[d] * a[d];
    for (int off = 16; off; off >>= 1) s += __shfl_xor_sync(0xffffffffu, s, off);
    if (lane == 0) C[k * 40 + col] = s;
}

__global__ void biasvec_kernel(const float* __restrict__ bsk, const float* __restrict__ b,
                               float* __restrict__ out) {
    int t = threadIdx.x;
    float s = bsk[t];
    for (int j = 0; j < RREL; j++) s += b[j * HID + t];
    out[t] = s;
}

// pack per head, k-pair layout
__global__ void prepack_h(const float* __restrict__ W, const float* __restrict__ Wsk,
                          uint32_t* __restrict__ Bp, int K, int KX) {
    int idx = blockIdx.x * blockDim.x + threadIdx.x;
    int kt2 = (RREL * K + KX) / 2;
    int total = HEADS * kt2 * DH;
    if (idx >= total) return;
    int n = idx & (DH - 1);
    int rest = idx >> 7;
    int kp = rest % kt2;
    int h = rest / kt2;
    float v[2];
    #pragma unroll
    for (int q = 0; q < 2; q++) {
        int k = 2 * kp + q;
        if (k < RREL * K) {
            int j = k / K, kk = k % K;
            v[q] = W[((size_t)j * K + kk) * HID + h * DH + n];
        } else {
            v[q] = Wsk[(size_t)(k - RREL * K) * HID + h * DH + n];
        }
    }
    __half2 p = __halves2half2(__float2half_rn(v[0]), __float2half_rn(v[1]));
    Bp[idx] = *(uint32_t*)&p;
}

// ---------------- mma.sync tf32 GEMM (optionally emits fp16 copy of A) ----------------
// Ah != nullptr requires grid.x == 1 && grid.z == 1.
template <int BN>
__global__ void __launch_bounds__(256, 2) tgemm(
    const float* __restrict__ A, int lda, size_t hsA,
    const float* __restrict__ B, size_t hsB,
    float* __restrict__ C, int ldc, size_t hsC,
    int M, int N, int K, const float* __restrict__ bias, int accum,
    __half* __restrict__ Ah) {
    constexpr int MF  = (BN == 128) ? 4 : 2;
    constexpr int NQ  = BN / 4;
    constexpr int ITB = BN / 64;
    __shared__ uint32_t As[2][16 * 128];
    __shared__ uint32_t Bs[2][16 * BN];
    A += (size_t)blockIdx.z * hsA;
    B += (size_t)blockIdx.z * hsB;
    C += (size_t)blockIdx.z * hsC;
    const int bm = blockIdx.y * 128, bn = blockIdx.x * BN;
    const int tid = threadIdx.x;
    const int lane = tid & 31, warp = tid >> 5;
    const int wm = (BN == 128) ? (warp >> 2) * 64 : (warp >> 1) * 32;
    const int wn = (BN == 128) ? (warp & 3) * 32 : (warp & 1) * 32;
    const int g = lane >> 2, ctg = lane & 3;
    const bool n_vec = ((N & 3) == 0);

    float acc[MF][4][4];
    #pragma unroll
    for (int mf = 0; mf < MF; mf++)
        #pragma unroll
        for (int nf = 0; nf < 4; nf++)
            #pragma unroll
            for (int q = 0; q < 4; q++) acc[mf][nf][q] = 0.f;

    float4 aReg[2];
    float  bReg[ITB][4];

    auto fetch = [&](int k0) {
        #pragma unroll
        for (int it = 0; it < 2; it++) {
            int idx = tid + it * 256;
            int r = idx >> 2, c4 = idx & 3;
            int gr = bm + r;
            aReg[it] = make_float4(0.f, 0.f, 0.f, 0.f);
            if (gr < M) {
                aReg[it] = *(const float4*)(A + (size_t)gr * lda + k0 + c4 * 4);
                if (Ah) {
                    __half2 p0 = __halves2half2(__float2half_rn(aReg[it].x),
                                                __float2half_rn(aReg[it].y));
                    __half2 p1 = __halves2half2(__float2half_rn(aReg[it].z),
                                                __float2half_rn(aReg[it].w));
                    *(uint2*)(Ah + (size_t)gr * lda + k0 + c4 * 4) =
                        make_uint2(*(uint32_t*)&p0, *(uint32_t*)&p1);
                }
            }
        }
        #pragma unroll
        for (int it = 0; it < ITB; it++) {
            int idx = tid + it * 256;
            int kk = idx / NQ, nq = idx % NQ;
            int gn = bn + nq * 4;
            const float* bp = B + (size_t)(k0 + kk) * N + gn;
            bReg[it][0] = bReg[it][1] = bReg[it][2] = bReg[it][3] = 0.f;
            if (n_vec && gn + 3 < N) {
                float4 v = *(const float4*)bp;
                bReg[it][0] = v.x; bReg[it][1] = v.y; bReg[it][2] = v.z; bReg[it][3] = v.w;
            } else {
                if (gn < N)     bReg[it][0] = bp[0];
                if (gn + 1 < N) bReg[it][1] = bp[1];
                if (gn + 2 < N) bReg[it][2] = bp[2];
                if (gn + 3 < N) bReg[it][3] = bp[3];
            }
        }
    };

    auto stage = [&](int buf) {
        #pragma unroll
        for (int it = 0; it < 2; it++) {
            int idx = tid + it * 256;
            int r = idx >> 2, c4 = idx & 3;
            uint32_t uv[4] = {f2tf32(aReg[it].x), f2tf32(aReg[it].y),
                              f2tf32(aReg[it].z), f2tf32(aReg[it].w)};
            #pragma unroll
            for (int s = 0; s < 4; s++) {
                int i = (s + lane) & 3;
                int kk = c4 * 4 + i;
                As[buf][kk * 128 + (r ^ (8 * (kk & 3)))] = uv[i];
            }
        }
        #pragma unroll
        for (int it = 0; it < ITB; it++) {
            int idx = tid + it * 256;
            int kk = idx / NQ, nq = idx % NQ;
            *(uint4*)&Bs[buf][kk * BN + ((nq * 4) ^ (8 * (kk & 3)))] =
                make_uint4(f2tf32(bReg[it][0]), f2tf32(bReg[it][1]),
                           f2tf32(bReg[it][2]), f2tf32(bReg[it][3]));
        }
    };

    const int nk = K >> 4;
    fetch(0);
    stage(0);
    if (nk > 1) fetch(16);
    __syncthreads();

    for (int ki = 0; ki < nk; ki++) {
        const int cur = ki & 1;
        if (ki + 1 < nk) {
            stage(cur ^ 1);
            if (ki + 2 < nk) fetch((ki + 2) << 4);
        }

        #pragma unroll
        for (int ks = 0; ks < 16; ks += 8) {
            uint32_t af[MF][4], bf[4][2];
            int kA0 = ks + ctg;
            int kA1 = ks + 4 + ctg;
            #pragma unroll
            for (int mf = 0; mf < MF; mf++) {
                int row = wm + mf * 16 + g;
                af[mf][0] = As[cur][kA0 * 128 + (row ^ (8 * ctg))];
                af[mf][1] = As[cur][kA0 * 128 + ((row + 8) ^ (8 * ctg))];
                af[mf][2] = As[cur][kA1 * 128 + (row ^ (8 * ctg))];
                af[mf][3] = As[cur][kA1 * 128 + ((row + 8) ^ (8 * ctg))];
            }
            #pragma unroll
            for (int nf = 0; nf < 4; nf++) {
                int col = wn + nf * 8 + g;
                bf[nf][0] = Bs[cur][kA0 * BN + (col ^ (8 * ctg))];
                bf[nf][1] = Bs[cur][kA1 * BN + (col ^ (8 * ctg))];
            }
            #pragma unroll
            for (int mf = 0; mf < MF; mf++)
                #pragma unroll
                for (int nf = 0; nf < 4; nf++)
                    mma_tf32(acc[mf][nf], af[mf], bf[nf]);
        }
        __syncthreads();
    }

    #pragma unroll
    for (int mf = 0; mf < MF; mf++) {
        #pragma unroll
        for (int half = 0; half < 2; half++) {
            int r = bm + wm + mf * 16 + g + half * 8;
            if (r >= M) continue;
            #pragma unroll
            for (int nf = 0; nf < 4; nf++) {
                int c = bn + wn + nf * 8 + ctg * 2;
                float v0 = acc[mf][nf][half * 2 + 0];
                float v1 = acc[mf][nf][half * 2 + 1];
                if (c < N) {
                    float base0 = accum ? C[(size_t)r * ldc + c] : 0.f;
                    C[(size_t)r * ldc + c] = base0 + v0 + (bias ? bias[c] : 0.f);
                }
                if (c + 1 < N) {
                    float base1 = accum ? C[(size_t)r * ldc + c + 1] : 0.f;
                    C[(size_t)r * ldc + c + 1] = base1 + v1 + (bias ? bias[c + 1] : 0.f);
                }
            }
        }
    }
}

// ---------------- fp16 cp.async head GEMM, BK=64, fused skip ----------------
#define ASH 36
#define BSH 136
#define HGH_SMEM (2 * (128 * ASH + 32 * BSH) * 4)

__global__ void __launch_bounds__(256, 2) hgemm(
    const __half* __restrict__ A1, int lda1, size_t hsA1,
    const __half* __restrict__ A2, int lda2,
    const uint32_t* __restrict__ Bp, size_t hsB,
    float* __restrict__ C, int ldc, size_t hsC,
    int M, int KA, int KX, const float* __restrict__ bias) {
    extern __shared__ uint32_t smu[];
    uint32_t* Asm[2] = {smu, smu + 128 * ASH};
    uint32_t* Bsm[2] = {smu + 2 * 128 * ASH, smu + 2 * 128 * ASH + 32 * BSH};
    A1 += (size_t)blockIdx.y * hsA1;
    Bp += (size_t)blockIdx.y * hsB;
    C  += (size_t)blockIdx.y * hsC;
    bias += (size_t)blockIdx.y * DH;
    const int bm = blockIdx.x * 128;
    const int tid = threadIdx.x, lane = tid & 31, warp = tid >> 5;
    const int wm = (warp >> 2) * 64, wn = (warp & 3) * 32;
    const int g = lane >> 2, ctg = lane & 3;

    float acc[4][4][4];
    #pragma unroll
    for (int mf = 0; mf < 4; mf++)
        #pragma unroll
        for (int nf = 0; nf < 4; nf++)
            #pragma unroll
            for (int q = 0; q < 4; q++) acc[mf][nf][q] = 0.f;

    auto issue = [&](int buf, int k0) {
        const __half* Ab;
        int ldx, kc;
        if (k0 < KA) { Ab = A1; ldx = lda1; kc = k0; }
        else         { Ab = A2; ldx = lda2; kc = k0 - KA; }
        #pragma unroll
        for (int it = 0; it < 4; it++) {
            int idx = tid + it * 256;
            int r = idx >> 3, c8 = idx & 7;
            const __half* src = Ab + (size_t)(bm + r) * ldx + kc + c8 * 8;
            uint32_t dst = (uint32_t)__cvta_generic_to_shared(&Asm[buf][r * ASH + c8 * 4]);
            int sz = (bm + r < M) ? 16 : 0;
            asm volatile("cp.async.cg.shared.global [%0], [%1], 16, %2;"
                         :: "r"(dst), "l"(src), "r"(sz));
        }
        int kp0 = k0 >> 1;
        #pragma unroll
        for (int it = 0; it < 4; it++) {
            int idx = tid + it * 256;
            int kp = idx >> 5, nq = idx & 31;
            const uint32_t* src = Bp + (size_t)(kp0 + kp) * 128 + nq * 4;
            uint32_t dst = (uint32_t)__cvta_generic_to_shared(&Bsm[buf][kp * BSH + nq * 4]);
            asm volatile("cp.async.cg.shared.global [%0], [%1], 16;" :: "r"(dst), "l"(src));
        }
        asm volatile("cp.async.commit_group;");
    };

    const int nk = (KA + KX) >> 6;
    issue(0, 0);
    issue(1, 64);
    asm volatile("cp.async.wait_group 1;");
    __syncthreads();

    for (int ki = 0; ki < nk; ki++) {
        const int cur = ki & 1;
        const uint32_t* Ab = Asm[cur];
        const uint32_t* Bb = Bsm[cur];

        #pragma unroll
        for (int kc2 = 0; kc2 < 4; kc2++) {
            int kb = kc2 * 8;
            uint32_t af[4][4], bf[4][2];
            #pragma unroll
            for (int mf = 0; mf < 4; mf++) {
                int row = wm + mf * 16 + g;
                af[mf][0] = Ab[row * ASH + kb + ctg];
                af[mf][1] = Ab[(row + 8) * ASH + kb + ctg];
                af[mf][2] = Ab[row * ASH + kb + 4 + ctg];
                af[mf][3] = Ab[(row + 8) * ASH + kb + 4 + ctg];
            }
            #pragma unroll
            for (int nf = 0; nf < 4; nf++) {
                int col = wn + nf * 8 + g;
                bf[nf][0] = Bb[(kb + ctg) * BSH + col];
                bf[nf][1] = Bb[(kb + 4 + ctg) * BSH + col];
            }
            #pragma unroll
            for (int mf = 0; mf < 4; mf++)
                #pragma unroll
                for (int nf = 0; nf < 4; nf++)
                    mma_f16(acc[mf][nf], af[mf], bf[nf]);
        }

        __syncthreads();
        if (ki + 2 < nk) issue(cur, (ki + 2) << 6);
        if (ki + 1 < nk) {
            if (ki + 2 < nk) asm volatile("cp.async.wait_group 1;");
            else             asm volatile("cp.async.wait_group 0;");
            __syncthreads();
        }
    }

    #pragma unroll
    for (int mf = 0; mf < 4; mf++) {
        #pragma unroll
        for (int half = 0; half < 2; half++) {
            int r = bm + wm + mf * 16 + g + half * 8;
            if (r >= M) continue;
            float* cr = C + (size_t)r * ldc;
            #pragma unroll
            for (int nf = 0; nf < 4; nf++) {
                int c = wn + nf * 8 + ctg * 2;
                cr[c]     = acc[mf][nf][half * 2 + 0] + bias[c];
                cr[c + 1] = acc[mf][nf][half * 2 + 1] + bias[c + 1];
            }
        }
    }
}

// ---------------- single-pass softmax; emits CSR-sorted alphas + esort ----------------
__global__ void alpha_kernel(const int* __restrict__ rowptr, const int* __restrict__ perm,
                             const int* __restrict__ esrc,
                             const float* __restrict__ SS,
                             float* __restrict__ alphas, int* __restrict__ esort,
                             float* __restrict__ den, int ndst) {
    int d = blockIdx.x * 8 + (threadIdx.x >> 5);
    if (d >= ndst) return;
    int lane = threadIdx.x & 31;
    for (int j = 0; j < RREL; j++) {
        int bin = d * RREL + j;
        int beg = rowptr[bin], end = rowptr[bin + 1];
        float sd[4];
        #pragma unroll
        for (int h = 0; h < 4; h++) sd[h] = SS[(size_t)d * 40 + 20 + j * 4 + h];

        float sm[4] = {0.f, 0.f, 0.f, 0.f};
        for (int i = beg + lane; i < end; i += 32) {
            int s = esrc[perm[i]];
            float ex[4];
            #pragma unroll
            for (int h = 0; h < 4; h++) {
                float sc = SS[(size_t)s * 40 + j * 4 + h] + sd[h];
                sc = sc > 0.f ? sc : 0.2f * sc;
                ex[h] = expf(sc);
                sm[h] += ex[h];
            }
            *(float4*)(alphas + (size_t)i * 4) = make_float4(ex[0], ex[1], ex[2], ex[3]);
            esort[i] = s;
        }
        #pragma unroll
        for (int h = 0; h < 4; h++)
            for (int off = 16; off; off >>= 1)
                sm[h] += __shfl_xor_sync(0xffffffffu, sm[h], off);
        if (lane == 0)
            *(float4*)(den + (size_t)bin * 4) = make_float4(sm[0], sm[1], sm[2], sm[3]);
    }
}

// ---------------- aggregate: sequential alphas/esort, fp16 row gather ----------------
template <int DIN_>
__global__ void __launch_bounds__(DIN_ / 4) aggx_kernel(
    const int* __restrict__ rowptr,
    const float* __restrict__ alphas, const int* __restrict__ esort,
    const float* __restrict__ den,
    const __half* __restrict__ Xh, __half* __restrict__ aggX) {
    int d = blockIdx.x, t = threadIdx.x;   // t < DIN_/4
    #pragma unroll
    for (int j = 0; j < RREL; j++) {
        int bin = d * RREL + j;
        float acc[HEADS][4];
        #pragma unroll
        for (int h = 0; h < HEADS; h++)
            #pragma unroll
            for (int c = 0; c < 4; c++) acc[h][c] = 0.f;

        int beg = rowptr[bin], end = rowptr[bin + 1];
        for (int i = beg; i < end; i++) {
            int s = esort[i];
            float4 al = *(const float4*)(alphas + (size_t)i * 4);
            uint2 pk = *(const uint2*)(Xh + (size_t)s * DIN_ + t * 4);
            float2 f0 = __half22float2(*(__half2*)&pk.x);
            float2 f1 = __half22float2(*(__half2*)&pk.y);
            float xv0 = f0.x, xv1 = f0.y, xv2 = f1.x, xv3 = f1.y;
            acc[0][0] += al.x * xv0; acc[0][1] += al.x * xv1;
            acc[0][2] += al.x * xv2; acc[0][3] += al.x * xv3;
            acc[1][0] += al.y * xv0; acc[1][1] += al.y * xv1;
            acc[1][2] += al.y * xv2; acc[1][3] += al.y * xv3;
            acc[2][0] += al.z * xv0; acc[2][1] += al.z * xv1;
            acc[2][2] += al.z * xv2; acc[2][3] += al.z * xv3;
            acc[3][0] += al.w * xv0; acc[3][1] += al.w * xv1;
            acc[3][2] += al.w * xv2; acc[3][3] += al.w * xv3;
        }
        float4 dn = *(const float4*)(den + (size_t)bin * 4);
        float rs[4] = {1.f / fmaxf(dn.x, 1e-16f), 1.f / fmaxf(dn.y, 1e-16f),
                       1.f / fmaxf(dn.z, 1e-16f), 1.f / fmaxf(dn.w, 1e-16f)};
        #pragma unroll
        for (int h = 0; h < HEADS; h++) {
            __half2 p0 = __halves2half2(__float2half_rn(acc[h][0] * rs[h]),
                                        __float2half_rn(acc[h][1] * rs[h]));
            __half2 p1 = __halves2half2(__float2half_rn(acc[h][2] * rs[h]),
                                        __float2half_rn(acc[h][3] * rs[h]));
            uint2 pk = make_uint2(*(uint32_t*)&p0, *(uint32_t*)&p1);
            *(uint2*)(aggX + ((size_t)(d * 4 + h)) * (RREL * DIN_) + j * DIN_ + t * 4) = pk;
        }
    }
}

// ---------------- batch-norm (partial-sum slab) ----------------
__global__ void bn_stats(const float* __restrict__ X, int n,
                         float* __restrict__ ps, float* __restrict__ pq) {
    int t = threadIdx.x;
    int rpb = (n + gridDim.x - 1) / gridDim.x;
    int r0 = blockIdx.x * rpb;
    int r1 = min(n, r0 + rpb);
    float s = 0.f, q = 0.f;
    for (int r = r0; r < r1; r++) {
        float v = X[(size_t)r * HID + t];
        s += v;
        q += v * v;
    }
    ps[blockIdx.x * HID + t] = s;
    pq[blockIdx.x * HID + t] = q;
}

__global__ void bn_final(const float* __restrict__ ps, const float* __restrict__ pq,
                         float n, float* __restrict__ mu, float* __restrict__ rstd) {
    int t = threadIdx.x;
    float s = 0.f, q = 0.f;
    #pragma unroll 8
    for (int b = 0; b < 64; b++) {
        s += ps[b * HID + t];
        q += pq[b * HID + t];
    }
    float m = s / n;
    float v = q / n - m * m;
    mu[t] = m;
    rstd[t] = rsqrtf(v + EPSBN);
}

__global__ void bn_apply(float* __restrict__ X, int n,
                         const float* __restrict__ g, const float* __restrict__ be,
                         const float* __restrict__ mu, const float* __restrict__ rstd, int act) {
    int idx = blockIdx.x * blockDim.x + threadIdx.x;
    int total = n * HID;
    if (idx >= total) return;
    int c = idx & (HID - 1);
    float v = X[idx];
    float y = g[c] * ((v - mu[c]) * rstd[c]) + be[c];
    X[idx] = (act == 0) ? (y > 0.f ? y : expm1f(y)) : fmaxf(y, 0.f);
}

// ---------------- host orchestration ----------------
static inline dim3 tg(int M, int N, int BN_, int Z = 1) {
    return dim3((N + BN_ - 1) / BN_, (M + 127) / 128, Z);
}

extern "C" void kernel_launch(void* const* d_in, const int* in_sizes, int n_in,
                              void* d_out, int out_size) {
    const float* x    = (const float*)d_in[0];
    const int*   es0  = (const int*)d_in[1];
    const int*   ed0  = (const int*)d_in[2];
    const int*   et0  = (const int*)d_in[3];
    const int*   es1  = (const int*)d_in[4];
    const int*   ed1  = (const int*)d_in[5];
    const int*   et1  = (const int*)d_in[6];
    const float* W0   = (const float*)d_in[7];
    const float* as0  = (const float*)d_in[8];
    const float* ad0  = (const float*)d_in[9];
    const float* b0   = (const float*)d_in[10];
    const float* Wsk0 = (const float*)d_in[11];
    const float* bsk0 = (const float*)d_in[12];
    const float* g0   = (const float*)d_in[13];
    const float* be0  = (const float*)d_in[14];
    const float* W1   = (const float*)d_in[15];
    const float* as1  = (const float*)d_in[16];
    const float* ad1  = (const float*)d_in[17];
    const float* b1   = (const float*)d_in[18];
    const float* Wsk1 = (const float*)d_in[19];
    const float* bsk1 = (const float*)d_in[20];
    const float* g1   = (const float*)d_in[21];
    const float* be1  = (const float*)d_in[22];
    const float* Wm1  = (const float*)d_in[23];
    const float* bm1  = (const float*)d_in[24];
    const float* gm   = (const float*)d_in[25];
    const float* bmn  = (const float*)d_in[26];
    const float* Wm2  = (const float*)d_in[27];
    const float* bm2  = (const float*)d_in[28];
    float* out = (float*)d_out;

    void *pAgg, *pBcP, *pXh, *pOh, *pSS, *pOut0, *pOut1, *pZ, *pAs, *pEs, *pDen, *pC, *pBias;
    void *pPS, *pPQ, *pMu, *pRs, *pRp, *pPerm, *pCnt, *pIncl, *pBsum;
    cudaGetSymbolAddress(&pAgg, g_aggX);
    cudaGetSymbolAddress(&pBcP, g_BcatP);
    cudaGetSymbolAddress(&pXh, g_xh);
    cudaGetSymbolAddress(&pOh, g_oh);
    cudaGetSymbolAddress(&pSS, g_SS);
    cudaGetSymbolAddress(&pOut0, g_out0);
    cudaGetSymbolAddress(&pOut1, g_out1);
    cudaGetSymbolAddress(&pZ, g_z);
    cudaGetSymbolAddress(&pAs, g_alphas);
    cudaGetSymbolAddress(&pEs, g_esort);
    cudaGetSymbolAddress(&pDen, g_den);
    cudaGetSymbolAddress(&pC, g_C);
    cudaGetSymbolAddress(&pBias, g_bias);
    cudaGetSymbolAddress(&pPS, g_ps);
    cudaGetSymbolAddress(&pPQ, g_pq);
    cudaGetSymbolAddress(&pMu, g_mu);
    cudaGetSymbolAddress(&pRs, g_rstd);
    cudaGetSymbolAddress(&pRp, g_rowptr);
    cudaGetSymbolAddress(&pPerm, g_perm);
    cudaGetSymbolAddress(&pCnt, g_cnt);
    cudaGetSymbolAddress(&pIncl, g_incl);
    cudaGetSymbolAddress(&pBsum, g_bsum);

    __half* aggX    = (__half*)pAgg;
    uint32_t* BcatP = (uint32_t*)pBcP;
    __half* xh      = (__half*)pXh;
    __half* oh      = (__half*)pOh;
    float* SS     = (float*)pSS;
    float* out0   = (float*)pOut0;
    float* out1   = (float*)pOut1;
    float* z      = (float*)pZ;
    float* alphas = (float*)pAs;
    int*   esort  = (int*)pEs;
    float* den    = (float*)pDen;
    float* C      = (float*)pC;
    float* bias   = (float*)pBias;
    float* ps     = (float*)pPS;
    float* pq     = (float*)pPQ;
    float* mu     = (float*)pMu;
    float* rstd   = (float*)pRs;
    int* rp       = (int*)pRp;
    int* perm     = (int*)pPerm;
    int* cnt      = (int*)pCnt;
    int* incl     = (int*)pIncl;
    int* bsum     = (int*)pBsum;

    cudaStream_t st = 0;
    const int NBA = (NBINSA + 255) / 256;

    cudaFuncSetAttribute(hgemm, cudaFuncAttributeMaxDynamicSharedMemorySize, HGH_SMEM);

    // ===== merged CSR (both layers) =====
    cudaMemsetAsync(cnt, 0, NBINSA * sizeof(int), st);
    hist2<<<(EA_ALL + 255) / 256, 256, 0, st>>>(ed0, et0, ed1, et1, cnt);
    scan1<<<NBA, 256, 0, st>>>(cnt, incl, bsum, NBINSA);
    scan2<<<1, 1024, 0, st>>>(bsum, NBA);
    scan3<<<NBA, 256, 0, st>>>(incl, cnt, bsum, rp, NBINSA);
    cudaMemsetAsync(cnt, 0, NBINSA * sizeof(int), st);
    scatter2<<<(EA_ALL + 255) / 256, 256, 0, st>>>(ed0, et0, ed1, et1, rp, cnt, perm);

    // ===== Layer 0: attention scores (emits xh) + softmax =====
    cmb_kernel<<<(DIN * 40 * 32 + 255) / 256, 256, 0, st>>>(W0, as0, ad0, C, DIN);
    tgemm<64><<<tg(N0, 40, 64), 256, 0, st>>>(x, DIN, 0, C, 0, SS, 40, 0, N0, 40, DIN,
                                              nullptr, 0, xh);
    alpha_kernel<<<(N1 + 7) / 8, 256, 0, st>>>(rp, perm, es0, SS, alphas, esort, den, N1);

    // ===== Layer 0: aggregate + fp16 fused (head | skip) GEMM =====
    biasvec_kernel<<<1, HID, 0, st>>>(bsk0, b0, bias);
    aggx_kernel<DIN><<<N1, DIN / 4, 0, st>>>(rp, alphas, esort, den, xh, aggX);
    prepack_h<<<(HEADS * ((RREL * DIN + DIN) / 2) * DH + 255) / 256, 256, 0, st>>>(
        W0, Wsk0, BcatP, DIN, DIN);
    hgemm<<<dim3((N1 + 127) / 128, HEADS), 256, HGH_SMEM, st>>>(
        aggX, HEADS * RREL * DIN, (size_t)RREL * DIN,
        xh, DIN,
        BcatP, (size_t)((RREL * DIN + DIN) / 2) * DH,
        out0, HID, (size_t)DH,
        N1, RREL * DIN, DIN, bias);

    // ===== Layer 0: BN + ELU =====
    bn_stats<<<64, HID, 0, st>>>(out0, N1, ps, pq);
    bn_final<<<1, HID, 0, st>>>(ps, pq, (float)N1, mu, rstd);
    bn_apply<<<(N1 * HID + 255) / 256, 256, 0, st>>>(out0, N1, g0, be0, mu, rstd, 0);

    // ===== Layer 1: attention scores (emits oh) + softmax =====
    cmb_kernel<<<(HID * 40 * 32 + 255) / 256, 256, 0, st>>>(W1, as1, ad1, C, HID);
    tgemm<64><<<tg(N1, 40, 64), 256, 0, st>>>(out0, HID, 0, C, 0, SS, 40, 0, N1, 40, HID,
                                              nullptr, 0, oh);
    alpha_kernel<<<(N2 + 7) / 8, 256, 0, st>>>(rp + NBINS0, perm, es1, SS, alphas, esort,
                                               den + (size_t)NBINS0 * 4, N2);

    // ===== Layer 1: aggregate + fp16 fused (head | skip) GEMM =====
    biasvec_kernel<<<1, HID, 0, st>>>(bsk1, b1, bias);
    aggx_kernel<HID><<<N2, HID / 4, 0, st>>>(rp + NBINS0, alphas, esort,
                                             den + (size_t)NBINS0 * 4, oh, aggX);
    prepack_h<<<(HEADS * ((RREL * HID + HID) / 2) * DH + 255) / 256, 256, 0, st>>>(
        W1, Wsk1, BcatP, HID, HID);
    hgemm<<<dim3((N2 + 127) / 128, HEADS), 256, HGH_SMEM, st>>>(
        aggX, HEADS * RREL * HID, (size_t)RREL * HID,
        oh, HID,
        BcatP, (size_t)((RREL * HID + HID) / 2) * DH,
        out1, HID, (size_t)DH,
        N2, RREL * HID, HID, bias);

    // ===== Layer 1: BN + ELU =====
    bn_stats<<<64, HID, 0, st>>>(out1, N2, ps, pq);
    bn_final<<<1, HID, 0, st>>>(ps, pq, (float)N2, mu, rstd);
    bn_apply<<<(N2 * HID + 255) / 256, 256, 0, st>>>(out1, N2, g1, be1, mu, rstd, 0);

    // ===== MLP head =====
    tgemm<128><<<tg(N2, HID, 128), 256, 0, st>>>(out1, HID, 0, Wm1, 0, z, HID, 0, N2, HID, HID,
                                                 bm1, 0, nullptr);
    bn_stats<<<64, HID, 0, st>>>(z, N2, ps, pq);
    bn_final<<<1, HID, 0, st>>>(ps, pq, (float)N2, mu, rstd);
    bn_apply<<<(N2 * HID + 255) / 256, 256, 0, st>>>(z, N2, gm, bmn, mu, rstd, 1);

    tgemm<64><<<tg(N2, OUTC, 64), 256, 0, st>>>(z, HID, 0, Wm2, 0, out, OUTC, 0, N2, OUTC, HID,
                                                bm2, 0, nullptr);
}

// round 16
// speedup vs baseline: 1.2378x; 1.0468x over previous
#include <cuda_runtime.h>
#include <cuda_fp16.h>
#include <math.h>
#include <stdint.h>

// ---------------- problem constants ----------------
#define N0    120000
#define E0    600000
#define N1    30000
#define E1    150000
#define N2    8000
#define DIN   768
#define HID   512
#define RREL  5
#define HEADS 4
#define DH    128
#define OUTC  153
#define EPSBN 1e-5f

#define NBINS0 (N1 * RREL)
#define NBINS1 (N2 * RREL)
#define NBINSA (NBINS0 + NBINS1)
#define EA_ALL (E0 + E1)

// ---------------- static scratch ----------------
__device__ __half   g_aggX[(size_t)N1 * HEADS * RREL * DIN];
__device__ uint32_t g_BcatP[(size_t)HEADS * ((RREL * DIN + DIN) / 2) * DH];
__device__ __half   g_xh[(size_t)N0 * DIN];     // x in fp16 (emitted by L0 score GEMM)
__device__ __half   g_oh[(size_t)N1 * HID];     // out0 in fp16 (emitted by L1 score GEMM)
__device__ float g_SS[(size_t)N0 * 40];
__device__ float g_out0[(size_t)N1 * HID];
__device__ float g_out1[(size_t)N2 * HID];
__device__ float g_z[(size_t)N2 * HID];
__device__ float g_alphas[(size_t)EA_ALL * 4];  // CSR-sorted unnormalized exp
__device__ int   g_esort[EA_ALL];               // CSR-sorted source index
__device__ int   g_bsorted[EA_ALL];             // CSR-sorted global bin index
__device__ float g_den[(size_t)NBINSA * 4];
__device__ float g_C[DIN * 40];
__device__ float g_bias[HID];
__device__ float g_ps[64 * HID];
__device__ float g_pq[64 * HID];
__device__ float g_mu[HID];
__device__ float g_rstd[HID];
__device__ int   g_rowptr[NBINSA + 1];
__device__ int   g_cnt[NBINSA];
__device__ int   g_incl[NBINSA];
__device__ int   g_bsum[1026];

// ---------------- tf32 / fp16 helpers ----------------
__device__ __forceinline__ uint32_t f2tf32(float x) {
    uint32_t u;
    asm("cvt.rna.tf32.f32 %0, %1;" : "=r"(u) : "f"(x));
    return u;
}

__device__ __forceinline__ void mma_tf32(float* d, const uint32_t* a, const uint32_t* b) {
    asm volatile(
        "mma.sync.aligned.m16n8k8.row.col.f32.tf32.tf32.f32 "
        "{%0,%1,%2,%3}, {%4,%5,%6,%7}, {%8,%9}, {%0,%1,%2,%3};\n"
        : "+f"(d[0]), "+f"(d[1]), "+f"(d[2]), "+f"(d[3])
        : "r"(a[0]), "r"(a[1]), "r"(a[2]), "r"(a[3]), "r"(b[0]), "r"(b[1]));
}

__device__ __forceinline__ void mma_f16(float* d, const uint32_t* a, const uint32_t* b) {
    asm volatile(
        "mma.sync.aligned.m16n8k16.row.col.f32.f16.f16.f32 "
        "{%0,%1,%2,%3}, {%4,%5,%6,%7}, {%8,%9}, {%0,%1,%2,%3};\n"
        : "+f"(d[0]), "+f"(d[1]), "+f"(d[2]), "+f"(d[3])
        : "r"(a[0]), "r"(a[1]), "r"(a[2]), "r"(a[3]), "r"(b[0]), "r"(b[1]));
}

// ---------------- merged CSR build ----------------
__global__ void hist2(const int* __restrict__ ed0, const int* __restrict__ et0,
                      const int* __restrict__ ed1, const int* __restrict__ et1,
                      int* __restrict__ cnt) {
    int i = blockIdx.x * blockDim.x + threadIdx.x;
    if (i < E0) {
        atomicAdd(&cnt[ed0[i] * RREL + et0[i]], 1);
    } else if (i < EA_ALL) {
        int e = i - E0;
        atomicAdd(&cnt[NBINS0 + ed1[e] * RREL + et1[e]], 1);
    }
}

__global__ void scan1(const int* __restrict__ cnt, int* __restrict__ incl,
                      int* __restrict__ bsum, int n) {
    __shared__ int sh[256];
    int t = threadIdx.x;
    int i = blockIdx.x * 256 + t;
    int v = (i < n) ? cnt[i] : 0;
    sh[t] = v;
    __syncthreads();
    #pragma unroll
    for (int off = 1; off < 256; off <<= 1) {
        int a = (t >= off) ? sh[t - off] : 0;
        __syncthreads();
        sh[t] += a;
        __syncthreads();
    }
    if (i < n) incl[i] = sh[t];
    if (t == 255) bsum[blockIdx.x] = sh[255];
}

__global__ void scan2(int* __restrict__ bsum, int nb) {
    __shared__ int sh[1024];
    int t = threadIdx.x;
    int v = (t < nb) ? bsum[t] : 0;
    sh[t] = v;
    __syncthreads();
    #pragma unroll
    for (int off = 1; off < 1024; off <<= 1) {
        int a = (t >= off) ? sh[t - off] : 0;
        __syncthreads();
        sh[t] += a;
        __syncthreads();
    }
    if (t < nb) bsum[t] = sh[t] - v;
    if (t == nb - 1) bsum[nb] = sh[t];
}

__global__ void scan3(const int* __restrict__ incl, const int* __restrict__ cnt,
                      const int* __restrict__ bsum, int* __restrict__ rowptr, int n) {
    int i = blockIdx.x * 256 + threadIdx.x;
    if (i < n) rowptr[i] = bsum[i >> 8] + incl[i] - cnt[i];
    if (i == 0) rowptr[n] = bsum[(n + 255) >> 8];
}

// scatter edges into CSR order, emitting sorted source + bin arrays directly
__global__ void scatter2(const int* __restrict__ ed0, const int* __restrict__ et0,
                         const int* __restrict__ es0,
                         const int* __restrict__ ed1, const int* __restrict__ et1,
                         const int* __restrict__ es1,
                         const int* __restrict__ rowptr, int* __restrict__ cur,
                         int* __restrict__ esort, int* __restrict__ bsorted) {
    int i = blockIdx.x * blockDim.x + threadIdx.x;
    int bin, src;
    if (i < E0) {
        bin = ed0[i] * RREL + et0[i];
        src = es0[i];
    } else if (i < EA_ALL) {
        int e = i - E0;
        bin = NBINS0 + ed1[e] * RREL + et1[e];
        src = es1[e];
    } else return;
    int p = atomicAdd(&cur[bin], 1);
    int slot = rowptr[bin] + p;
    esort[slot] = src;
    bsorted[slot] = bin;
}

// ---------------- combined score projection ----------------
__global__ void cmb_kernel(const float* __restrict__ W, const float* __restrict__ as_,
                           const float* __restrict__ ad_, float* __restrict__ C, int K) {
    int gw = (blockIdx.x * blockDim.x + threadIdx.x) >> 5;
    int lane = threadIdx.x & 31;
    if (gw >= K * 40) return;
    int k = gw / 40, col = gw % 40;
    int jh = (col < 20) ? col : col - 20;
    int j = jh / 4, h = jh % 4;
    const float* a = ((col < 20) ? as_ : ad_) + (size_t)(j * 4 + h) * DH;
    const float* w = W + ((size_t)j * K + k) * HID + h * DH;
    float s = 0.f;
    #pragma unroll
    for (int d = lane; d < DH; d += 32) s += w[d] * a[d];
    for (int off = 16; off; off >>= 1) s += __shfl_xor_sync(0xffffffffu, s, off);
    if (lane == 0) C[k * 40 + col] = s;
}

__global__ void biasvec_kernel(const float* __restrict__ bsk, const float* __restrict__ b,
                               float* __restrict__ out) {
    int t = threadIdx.x;
    float s = bsk[t];
    for (int j = 0; j < RREL; j++) s += b[j * HID + t];
    out[t] = s;
}

// pack per head, k-pair layout
__global__ void prepack_h(const float* __restrict__ W, const float* __restrict__ Wsk,
                          uint32_t* __restrict__ Bp, int K, int KX) {
    int idx = blockIdx.x * blockDim.x + threadIdx.x;
    int kt2 = (RREL * K + KX) / 2;
    int total = HEADS * kt2 * DH;
    if (idx >= total) return;
    int n = idx & (DH - 1);
    int rest = idx >> 7;
    int kp = rest % kt2;
    int h = rest / kt2;
    float v[2];
    #pragma unroll
    for (int q = 0; q < 2; q++) {
        int k = 2 * kp + q;
        if (k < RREL * K) {
            int j = k / K, kk = k % K;
            v[q] = W[((size_t)j * K + kk) * HID + h * DH + n];
        } else {
            v[q] = Wsk[(size_t)(k - RREL * K) * HID + h * DH + n];
        }
    }
    __half2 p = __halves2half2(__float2half_rn(v[0]), __float2half_rn(v[1]));
    Bp[idx] = *(uint32_t*)&p;
}

// ---------------- mma.sync tf32 GEMM (optionally emits fp16 copy of A) ----------------
// Ah != nullptr requires grid.x == 1 && grid.z == 1.
template <int BN>
__global__ void __launch_bounds__(256, 2) tgemm(
    const float* __restrict__ A, int lda, size_t hsA,
    const float* __restrict__ B, size_t hsB,
    float* __restrict__ C, int ldc, size_t hsC,
    int M, int N, int K, const float* __restrict__ bias, int accum,
    __half* __restrict__ Ah) {
    constexpr int MF  = (BN == 128) ? 4 : 2;
    constexpr int NQ  = BN / 4;
    constexpr int ITB = BN / 64;
    __shared__ uint32_t As[2][16 * 128];
    __shared__ uint32_t Bs[2][16 * BN];
    A += (size_t)blockIdx.z * hsA;
    B += (size_t)blockIdx.z * hsB;
    C += (size_t)blockIdx.z * hsC;
    const int bm = blockIdx.y * 128, bn = blockIdx.x * BN;
    const int tid = threadIdx.x;
    const int lane = tid & 31, warp = tid >> 5;
    const int wm = (BN == 128) ? (warp >> 2) * 64 : (warp >> 1) * 32;
    const int wn = (BN == 128) ? (warp & 3) * 32 : (warp & 1) * 32;
    const int g = lane >> 2, ctg = lane & 3;
    const bool n_vec = ((N & 3) == 0);

    float acc[MF][4][4];
    #pragma unroll
    for (int mf = 0; mf < MF; mf++)
        #pragma unroll
        for (int nf = 0; nf < 4; nf++)
            #pragma unroll
            for (int q = 0; q < 4; q++) acc[mf][nf][q] = 0.f;

    float4 aReg[2];
    float  bReg[ITB][4];

    auto fetch = [&](int k0) {
        #pragma unroll
        for (int it = 0; it < 2; it++) {
            int idx = tid + it * 256;
            int r = idx >> 2, c4 = idx & 3;
            int gr = bm + r;
            aReg[it] = make_float4(0.f, 0.f, 0.f, 0.f);
            if (gr < M) {
                aReg[it] = *(const float4*)(A + (size_t)gr * lda + k0 + c4 * 4);
                if (Ah) {
                    __half2 p0 = __halves2half2(__float2half_rn(aReg[it].x),
                                                __float2half_rn(aReg[it].y));
                    __half2 p1 = __halves2half2(__float2half_rn(aReg[it].z),
                                                __float2half_rn(aReg[it].w));
                    *(uint2*)(Ah + (size_t)gr * lda + k0 + c4 * 4) =
                        make_uint2(*(uint32_t*)&p0, *(uint32_t*)&p1);
                }
            }
        }
        #pragma unroll
        for (int it = 0; it < ITB; it++) {
            int idx = tid + it * 256;
            int kk = idx / NQ, nq = idx % NQ;
            int gn = bn + nq * 4;
            const float* bp = B + (size_t)(k0 + kk) * N + gn;
            bReg[it][0] = bReg[it][1] = bReg[it][2] = bReg[it][3] = 0.f;
            if (n_vec && gn + 3 < N) {
                float4 v = *(const float4*)bp;
                bReg[it][0] = v.x; bReg[it][1] = v.y; bReg[it][2] = v.z; bReg[it][3] = v.w;
            } else {
                if (gn < N)     bReg[it][0] = bp[0];
                if (gn + 1 < N) bReg[it][1] = bp[1];
                if (gn + 2 < N) bReg[it][2] = bp[2];
                if (gn + 3 < N) bReg[it][3] = bp[3];
            }
        }
    };

    auto stage = [&](int buf) {
        #pragma unroll
        for (int it = 0; it < 2; it++) {
            int idx = tid + it * 256;
            int r = idx >> 2, c4 = idx & 3;
            uint32_t uv[4] = {f2tf32(aReg[it].x), f2tf32(aReg[it].y),
                              f2tf32(aReg[it].z), f2tf32(aReg[it].w)};
            #pragma unroll
            for (int s = 0; s < 4; s++) {
                int i = (s + lane) & 3;
                int kk = c4 * 4 + i;
                As[buf][kk * 128 + (r ^ (8 * (kk & 3)))] = uv[i];
            }
        }
        #pragma unroll
        for (int it = 0; it < ITB; it++) {
            int idx = tid + it * 256;
            int kk = idx / NQ, nq = idx % NQ;
            *(uint4*)&Bs[buf][kk * BN + ((nq * 4) ^ (8 * (kk & 3)))] =
                make_uint4(f2tf32(bReg[it][0]), f2tf32(bReg[it][1]),
                           f2tf32(bReg[it][2]), f2tf32(bReg[it][3]));
        }
    };

    const int nk = K >> 4;
    fetch(0);
    stage(0);
    if (nk > 1) fetch(16);
    __syncthreads();

    for (int ki = 0; ki < nk; ki++) {
        const int cur = ki & 1;
        if (ki + 1 < nk) {
            stage(cur ^ 1);
            if (ki + 2 < nk) fetch((ki + 2) << 4);
        }

        #pragma unroll
        for (int ks = 0; ks < 16; ks += 8) {
            uint32_t af[MF][4], bf[4][2];
            int kA0 = ks + ctg;
            int kA1 = ks + 4 + ctg;
            #pragma unroll
            for (int mf = 0; mf < MF; mf++) {
                int row = wm + mf * 16 + g;
                af[mf][0] = As[cur][kA0 * 128 + (row ^ (8 * ctg))];
                af[mf][1] = As[cur][kA0 * 128 + ((row + 8) ^ (8 * ctg))];
                af[mf][2] = As[cur][kA1 * 128 + (row ^ (8 * ctg))];
                af[mf][3] = As[cur][kA1 * 128 + ((row + 8) ^ (8 * ctg))];
            }
            #pragma unroll
            for (int nf = 0; nf < 4; nf++) {
                int col = wn + nf * 8 + g;
                bf[nf][0] = Bs[cur][kA0 * BN + (col ^ (8 * ctg))];
                bf[nf][1] = Bs[cur][kA1 * BN + (col ^ (8 * ctg))];
            }
            #pragma unroll
            for (int mf = 0; mf < MF; mf++)
                #pragma unroll
                for (int nf = 0; nf < 4; nf++)
                    mma_tf32(acc[mf][nf], af[mf], bf[nf]);
        }
        __syncthreads();
    }

    #pragma unroll
    for (int mf = 0; mf < MF; mf++) {
        #pragma unroll
        for (int half = 0; half < 2; half++) {
            int r = bm + wm + mf * 16 + g + half * 8;
            if (r >= M) continue;
            #pragma unroll
            for (int nf = 0; nf < 4; nf++) {
                int c = bn + wn + nf * 8 + ctg * 2;
                float v0 = acc[mf][nf][half * 2 + 0];
                float v1 = acc[mf][nf][half * 2 + 1];
                if (c < N) {
                    float base0 = accum ? C[(size_t)r * ldc + c] : 0.f;
                    C[(size_t)r * ldc + c] = base0 + v0 + (bias ? bias[c] : 0.f);
                }
                if (c + 1 < N) {
                    float base1 = accum ? C[(size_t)r * ldc + c + 1] : 0.f;
                    C[(size_t)r * ldc + c + 1] = base1 + v1 + (bias ? bias[c + 1] : 0.f);
                }
            }
        }
    }
}

// ---------------- fp16 cp.async head GEMM, BK=64, fused skip ----------------
#define ASH 36
#define BSH 136
#define HGH_SMEM (2 * (128 * ASH + 32 * BSH) * 4)

__global__ void __launch_bounds__(256, 2) hgemm(
    const __half* __restrict__ A1, int lda1, size_t hsA1,
    const __half* __restrict__ A2, int lda2,
    const uint32_t* __restrict__ Bp, size_t hsB,
    float* __restrict__ C, int ldc, size_t hsC,
    int M, int KA, int KX, const float* __restrict__ bias) {
    extern __shared__ uint32_t smu[];
    uint32_t* Asm[2] = {smu, smu + 128 * ASH};
    uint32_t* Bsm[2] = {smu + 2 * 128 * ASH, smu + 2 * 128 * ASH + 32 * BSH};
    A1 += (size_t)blockIdx.y * hsA1;
    Bp += (size_t)blockIdx.y * hsB;
    C  += (size_t)blockIdx.y * hsC;
    bias += (size_t)blockIdx.y * DH;
    const int bm = blockIdx.x * 128;
    const int tid = threadIdx.x, lane = tid & 31, warp = tid >> 5;
    const int wm = (warp >> 2) * 64, wn = (warp & 3) * 32;
    const int g = lane >> 2, ctg = lane & 3;

    float acc[4][4][4];
    #pragma unroll
    for (int mf = 0; mf < 4; mf++)
        #pragma unroll
        for (int nf = 0; nf < 4; nf++)
            #pragma unroll
            for (int q = 0; q < 4; q++) acc[mf][nf][q] = 0.f;

    auto issue = [&](int buf, int k0) {
        const __half* Ab;
        int ldx, kc;
        if (k0 < KA) { Ab = A1; ldx = lda1; kc = k0; }
        else         { Ab = A2; ldx = lda2; kc = k0 - KA; }
        #pragma unroll
        for (int it = 0; it < 4; it++) {
            int idx = tid + it * 256;
            int r = idx >> 3, c8 = idx & 7;
            const __half* src = Ab + (size_t)(bm + r) * ldx + kc + c8 * 8;
            uint32_t dst = (uint32_t)__cvta_generic_to_shared(&Asm[buf][r * ASH + c8 * 4]);
            int sz = (bm + r < M) ? 16 : 0;
            asm volatile("cp.async.cg.shared.global [%0], [%1], 16, %2;"
                         :: "r"(dst), "l"(src), "r"(sz));
        }
        int kp0 = k0 >> 1;
        #pragma unroll
        for (int it = 0; it < 4; it++) {
            int idx = tid + it * 256;
            int kp = idx >> 5, nq = idx & 31;
            const uint32_t* src = Bp + (size_t)(kp0 + kp) * 128 + nq * 4;
            uint32_t dst = (uint32_t)__cvta_generic_to_shared(&Bsm[buf][kp * BSH + nq * 4]);
            asm volatile("cp.async.cg.shared.global [%0], [%1], 16;" :: "r"(dst), "l"(src));
        }
        asm volatile("cp.async.commit_group;");
    };

    const int nk = (KA + KX) >> 6;
    issue(0, 0);
    issue(1, 64);
    asm volatile("cp.async.wait_group 1;");
    __syncthreads();

    for (int ki = 0; ki < nk; ki++) {
        const int cur = ki & 1;
        const uint32_t* Ab = Asm[cur];
        const uint32_t* Bb = Bsm[cur];

        #pragma unroll
        for (int kc2 = 0; kc2 < 4; kc2++) {
            int kb = kc2 * 8;
            uint32_t af[4][4], bf[4][2];
            #pragma unroll
            for (int mf = 0; mf < 4; mf++) {
                int row = wm + mf * 16 + g;
                af[mf][0] = Ab[row * ASH + kb + ctg];
                af[mf][1] = Ab[(row + 8) * ASH + kb + ctg];
                af[mf][2] = Ab[row * ASH + kb + 4 + ctg];
                af[mf][3] = Ab[(row + 8) * ASH + kb + 4 + ctg];
            }
            #pragma unroll
            for (int nf = 0; nf < 4; nf++) {
                int col = wn + nf * 8 + g;
                bf[nf][0] = Bb[(kb + ctg) * BSH + col];
                bf[nf][1] = Bb[(kb + 4 + ctg) * BSH + col];
            }
            #pragma unroll
            for (int mf = 0; mf < 4; mf++)
                #pragma unroll
                for (int nf = 0; nf < 4; nf++)
                    mma_f16(acc[mf][nf], af[mf], bf[nf]);
        }

        __syncthreads();
        if (ki + 2 < nk) issue(cur, (ki + 2) << 6);
        if (ki + 1 < nk) {
            if (ki + 2 < nk) asm volatile("cp.async.wait_group 1;");
            else             asm volatile("cp.async.wait_group 0;");
            __syncthreads();
        }
    }

    #pragma unroll
    for (int mf = 0; mf < 4; mf++) {
        #pragma unroll
        for (int half = 0; half < 2; half++) {
            int r = bm + wm + mf * 16 + g + half * 8;
            if (r >= M) continue;
            float* cr = C + (size_t)r * ldc;
            #pragma unroll
            for (int nf = 0; nf < 4; nf++) {
                int c = wn + nf * 8 + ctg * 2;
                cr[c]     = acc[mf][nf][half * 2 + 0] + bias[c];
                cr[c + 1] = acc[mf][nf][half * 2 + 1] + bias[c + 1];
            }
        }
    }
}

// ---------------- thread-per-edge exp(leaky(score)) ----------------
__global__ void alphaA(const int* __restrict__ esort, const int* __restrict__ bsorted,
                       const float* __restrict__ SS, float* __restrict__ alphas,
                       int ebeg, int ecount, int binoff) {
    int i = blockIdx.x * blockDim.x + threadIdx.x;
    if (i >= ecount) return;
    i += ebeg;
    int s = esort[i];
    int bin = bsorted[i] - binoff;
    int d = bin / RREL, j = bin % RREL;
    const float* ssrow = SS + (size_t)s * 40 + j * 4;
    const float* sdrow = SS + (size_t)d * 40 + 20 + j * 4;
    float ex[4];
    #pragma unroll
    for (int h = 0; h < 4; h++) {
        float sc = ssrow[h] + sdrow[h];
        sc = sc > 0.f ? sc : 0.2f * sc;
        ex[h] = expf(sc);
    }
    *(float4*)(alphas + (size_t)i * 4) = make_float4(ex[0], ex[1], ex[2], ex[3]);
}

// ---------------- thread-per-bin denominator ----------------
__global__ void denB(const int* __restrict__ rowptr, const float* __restrict__ alphas,
                     float* __restrict__ den, int binbeg, int nbins) {
    int b = blockIdx.x * blockDim.x + threadIdx.x;
    if (b >= nbins) return;
    b += binbeg;
    int beg = rowptr[b], end = rowptr[b + 1];
    float s0 = 0.f, s1 = 0.f, s2 = 0.f, s3 = 0.f;
    for (int i = beg; i < end; i++) {
        float4 a = *(const float4*)(alphas + (size_t)i * 4);
        s0 += a.x; s1 += a.y; s2 += a.z; s3 += a.w;
    }
    *(float4*)(den + (size_t)b * 4) = make_float4(s0, s1, s2, s3);
}

// ---------------- aggregate: sequential alphas/esort, fp16 row gather, 2x unroll ----------------
template <int DIN_>
__global__ void __launch_bounds__(DIN_ / 4) aggx_kernel(
    const int* __restrict__ rowptr,
    const float* __restrict__ alphas, const int* __restrict__ esort,
    const float* __restrict__ den,
    const __half* __restrict__ Xh, __half* __restrict__ aggX) {
    int d = blockIdx.x, t = threadIdx.x;   // t < DIN_/4
    #pragma unroll
    for (int j = 0; j < RREL; j++) {
        int bin = d * RREL + j;
        float acc[HEADS][4];
        #pragma unroll
        for (int h = 0; h < HEADS; h++)
            #pragma unroll
            for (int c = 0; c < 4; c++) acc[h][c] = 0.f;

        int beg = rowptr[bin], end = rowptr[bin + 1];
        int i = beg;
        for (; i + 1 < end; i += 2) {
            int s0 = esort[i], s1 = esort[i + 1];
            float4 al0 = *(const float4*)(alphas + (size_t)i * 4);
            float4 al1 = *(const float4*)(alphas + (size_t)(i + 1) * 4);
            uint2 pk0 = *(const uint2*)(Xh + (size_t)s0 * DIN_ + t * 4);
            uint2 pk1 = *(const uint2*)(Xh + (size_t)s1 * DIN_ + t * 4);
            float2 a0 = __half22float2(*(__half2*)&pk0.x);
            float2 a1 = __half22float2(*(__half2*)&pk0.y);
            float2 b0 = __half22float2(*(__half2*)&pk1.x);
            float2 b1 = __half22float2(*(__half2*)&pk1.y);
            acc[0][0] += al0.x * a0.x + al1.x * b0.x;
            acc[0][1] += al0.x * a0.y + al1.x * b0.y;
            acc[0][2] += al0.x * a1.x + al1.x * b1.x;
            acc[0][3] += al0.x * a1.y + al1.x * b1.y;
            acc[1][0] += al0.y * a0.x + al1.y * b0.x;
            acc[1][1] += al0.y * a0.y + al1.y * b0.y;
            acc[1][2] += al0.y * a1.x + al1.y * b1.x;
            acc[1][3] += al0.y * a1.y + al1.y * b1.y;
            acc[2][0] += al0.z * a0.x + al1.z * b0.x;
            acc[2][1] += al0.z * a0.y + al1.z * b0.y;
            acc[2][2] += al0.z * a1.x + al1.z * b1.x;
            acc[2][3] += al0.z * a1.y + al1.z * b1.y;
            acc[3][0] += al0.w * a0.x + al1.w * b0.x;
            acc[3][1] += al0.w * a0.y + al1.w * b0.y;
            acc[3][2] += al0.w * a1.x + al1.w * b1.x;
            acc[3][3] += al0.w * a1.y + al1.w * b1.y;
        }
        if (i < end) {
            int s = esort[i];
            float4 al = *(const float4*)(alphas + (size_t)i * 4);
            uint2 pk = *(const uint2*)(Xh + (size_t)s * DIN_ + t * 4);
            float2 f0 = __half22float2(*(__half2*)&pk.x);
            float2 f1 = __half22float2(*(__half2*)&pk.y);
            acc[0][0] += al.x * f0.x; acc[0][1] += al.x * f0.y;
            acc[0][2] += al.x * f1.x; acc[0][3] += al.x * f1.y;
            acc[1][0] += al.y * f0.x; acc[1][1] += al.y * f0.y;
            acc[1][2] += al.y * f1.x; acc[1][3] += al.y * f1.y;
            acc[2][0] += al.z * f0.x; acc[2][1] += al.z * f0.y;
            acc[2][2] += al.z * f1.x; acc[2][3] += al.z * f1.y;
            acc[3][0] += al.w * f0.x; acc[3][1] += al.w * f0.y;
            acc[3][2] += al.w * f1.x; acc[3][3] += al.w * f1.y;
        }
        float4 dn = *(const float4*)(den + (size_t)bin * 4);
        float rs[4] = {1.f / fmaxf(dn.x, 1e-16f), 1.f / fmaxf(dn.y, 1e-16f),
                       1.f / fmaxf(dn.z, 1e-16f), 1.f / fmaxf(dn.w, 1e-16f)};
        #pragma unroll
        for (int h = 0; h < HEADS; h++) {
            __half2 p0 = __halves2half2(__float2half_rn(acc[h][0] * rs[h]),
                                        __float2half_rn(acc[h][1] * rs[h]));
            __half2 p1 = __halves2half2(__float2half_rn(acc[h][2] * rs[h]),
                                        __float2half_rn(acc[h][3] * rs[h]));
            uint2 pk = make_uint2(*(uint32_t*)&p0, *(uint32_t*)&p1);
            *(uint2*)(aggX + ((size_t)(d * 4 + h)) * (RREL * DIN_) + j * DIN_ + t * 4) = pk;
        }
    }
}

// ---------------- batch-norm (partial-sum slab) ----------------
__global__ void bn_stats(const float* __restrict__ X, int n,
                         float* __restrict__ ps, float* __restrict__ pq) {
    int t = threadIdx.x;
    int rpb = (n + gridDim.x - 1) / gridDim.x;
    int r0 = blockIdx.x * rpb;
    int r1 = min(n, r0 + rpb);
    float s = 0.f, q = 0.f;
    for (int r = r0; r < r1; r++) {
        float v = X[(size_t)r * HID + t];
        s += v;
        q += v * v;
    }
    ps[blockIdx.x * HID + t] = s;
    pq[blockIdx.x * HID + t] = q;
}

__global__ void bn_final(const float* __restrict__ ps, const float* __restrict__ pq,
                         float n, float* __restrict__ mu, float* __restrict__ rstd) {
    int t = threadIdx.x;
    float s = 0.f, q = 0.f;
    #pragma unroll 8
    for (int b = 0; b < 64; b++) {
        s += ps[b * HID + t];
        q += pq[b * HID + t];
    }
    float m = s / n;
    float v = q / n - m * m;
    mu[t] = m;
    rstd[t] = rsqrtf(v + EPSBN);
}

__global__ void bn_apply(float* __restrict__ X, int n,
                         const float* __restrict__ g, const float* __restrict__ be,
                         const float* __restrict__ mu, const float* __restrict__ rstd, int act) {
    int idx = blockIdx.x * blockDim.x + threadIdx.x;
    int total = n * HID;
    if (idx >= total) return;
    int c = idx & (HID - 1);
    float v = X[idx];
    float y = g[c] * ((v - mu[c]) * rstd[c]) + be[c];
    X[idx] = (act == 0) ? (y > 0.f ? y : expm1f(y)) : fmaxf(y, 0.f);
}

// ---------------- host orchestration ----------------
static inline dim3 tg(int M, int N, int BN_, int Z = 1) {
    return dim3((N + BN_ - 1) / BN_, (M + 127) / 128, Z);
}

extern "C" void kernel_launch(void* const* d_in, const int* in_sizes, int n_in,
                              void* d_out, int out_size) {
    const float* x    = (const float*)d_in[0];
    const int*   es0  = (const int*)d_in[1];
    const int*   ed0  = (const int*)d_in[2];
    const int*   et0  = (const int*)d_in[3];
    const int*   es1  = (const int*)d_in[4];
    const int*   ed1  = (const int*)d_in[5];
    const int*   et1  = (const int*)d_in[6];
    const float* W0   = (const float*)d_in[7];
    const float* as0  = (const float*)d_in[8];
    const float* ad0  = (const float*)d_in[9];
    const float* b0   = (const float*)d_in[10];
    const float* Wsk0 = (const float*)d_in[11];
    const float* bsk0 = (const float*)d_in[12];
    const float* g0   = (const float*)d_in[13];
    const float* be0  = (const float*)d_in[14];
    const float* W1   = (const float*)d_in[15];
    const float* as1  = (const float*)d_in[16];
    const float* ad1  = (const float*)d_in[17];
    const float* b1   = (const float*)d_in[18];
    const float* Wsk1 = (const float*)d_in[19];
    const float* bsk1 = (const float*)d_in[20];
    const float* g1   = (const float*)d_in[21];
    const float* be1  = (const float*)d_in[22];
    const float* Wm1  = (const float*)d_in[23];
    const float* bm1  = (const float*)d_in[24];
    const float* gm   = (const float*)d_in[25];
    const float* bmn  = (const float*)d_in[26];
    const float* Wm2  = (const float*)d_in[27];
    const float* bm2  = (const float*)d_in[28];
    float* out = (float*)d_out;

    void *pAgg, *pBcP, *pXh, *pOh, *pSS, *pOut0, *pOut1, *pZ, *pAs, *pEs, *pBs, *pDen, *pC, *pBias;
    void *pPS, *pPQ, *pMu, *pRs, *pRp, *pCnt, *pIncl, *pBsum;
    cudaGetSymbolAddress(&pAgg, g_aggX);
    cudaGetSymbolAddress(&pBcP, g_BcatP);
    cudaGetSymbolAddress(&pXh, g_xh);
    cudaGetSymbolAddress(&pOh, g_oh);
    cudaGetSymbolAddress(&pSS, g_SS);
    cudaGetSymbolAddress(&pOut0, g_out0);
    cudaGetSymbolAddress(&pOut1, g_out1);
    cudaGetSymbolAddress(&pZ, g_z);
    cudaGetSymbolAddress(&pAs, g_alphas);
    cudaGetSymbolAddress(&pEs, g_esort);
    cudaGetSymbolAddress(&pBs, g_bsorted);
    cudaGetSymbolAddress(&pDen, g_den);
    cudaGetSymbolAddress(&pC, g_C);
    cudaGetSymbolAddress(&pBias, g_bias);
    cudaGetSymbolAddress(&pPS, g_ps);
    cudaGetSymbolAddress(&pPQ, g_pq);
    cudaGetSymbolAddress(&pMu, g_mu);
    cudaGetSymbolAddress(&pRs, g_rstd);
    cudaGetSymbolAddress(&pRp, g_rowptr);
    cudaGetSymbolAddress(&pCnt, g_cnt);
    cudaGetSymbolAddress(&pIncl, g_incl);
    cudaGetSymbolAddress(&pBsum, g_bsum);

    __half* aggX    = (__half*)pAgg;
    uint32_t* BcatP = (uint32_t*)pBcP;
    __half* xh      = (__half*)pXh;
    __half* oh      = (__half*)pOh;
    float* SS      = (float*)pSS;
    float* out0    = (float*)pOut0;
    float* out1    = (float*)pOut1;
    float* z       = (float*)pZ;
    float* alphas  = (float*)pAs;
    int*   esort   = (int*)pEs;
    int*   bsorted = (int*)pBs;
    float* den     = (float*)pDen;
    float* C       = (float*)pC;
    float* bias    = (float*)pBias;
    float* ps      = (float*)pPS;
    float* pq      = (float*)pPQ;
    float* mu      = (float*)pMu;
    float* rstd    = (float*)pRs;
    int* rp        = (int*)pRp;
    int* cnt       = (int*)pCnt;
    int* incl      = (int*)pIncl;
    int* bsum      = (int*)pBsum;

    cudaStream_t st = 0;
    const int NBA = (NBINSA + 255) / 256;

    cudaFuncSetAttribute(hgemm, cudaFuncAttributeMaxDynamicSharedMemorySize, HGH_SMEM);

    // ===== merged CSR (both layers) =====
    cudaMemsetAsync(cnt, 0, NBINSA * sizeof(int), st);
    hist2<<<(EA_ALL + 255) / 256, 256, 0, st>>>(ed0, et0, ed1, et1, cnt);
    scan1<<<NBA, 256, 0, st>>>(cnt, incl, bsum, NBINSA);
    scan2<<<1, 1024, 0, st>>>(bsum, NBA);
    scan3<<<NBA, 256, 0, st>>>(incl, cnt, bsum, rp, NBINSA);
    cudaMemsetAsync(cnt, 0, NBINSA * sizeof(int), st);
    scatter2<<<(EA_ALL + 255) / 256, 256, 0, st>>>(ed0, et0, es0, ed1, et1, es1,
                                                   rp, cnt, esort, bsorted);

    // ===== Layer 0: attention scores (emits xh) + softmax =====
    cmb_kernel<<<(DIN * 40 * 32 + 255) / 256, 256, 0, st>>>(W0, as0, ad0, C, DIN);
    tgemm<64><<<tg(N0, 40, 64), 256, 0, st>>>(x, DIN, 0, C, 0, SS, 40, 0, N0, 40, DIN,
                                              nullptr, 0, xh);
    alphaA<<<(E0 + 255) / 256, 256, 0, st>>>(esort, bsorted, SS, alphas, 0, E0, 0);
    denB<<<(NBINS0 + 255) / 256, 256, 0, st>>>(rp, alphas, den, 0, NBINS0);

    // ===== Layer 0: aggregate + fp16 fused (head | skip) GEMM =====
    biasvec_kernel<<<1, HID, 0, st>>>(bsk0, b0, bias);
    aggx_kernel<DIN><<<N1, DIN / 4, 0, st>>>(rp, alphas, esort, den, xh, aggX);
    prepack_h<<<(HEADS * ((RREL * DIN + DIN) / 2) * DH + 255) / 256, 256, 0, st>>>(
        W0, Wsk0, BcatP, DIN, DIN);
    hgemm<<<dim3((N1 + 127) / 128, HEADS), 256, HGH_SMEM, st>>>(
        aggX, HEADS * RREL * DIN, (size_t)RREL * DIN,
        xh, DIN,
        BcatP, (size_t)((RREL * DIN + DIN) / 2) * DH,
        out0, HID, (size_t)DH,
        N1, RREL * DIN, DIN, bias);

    // ===== Layer 0: BN + ELU =====
    bn_stats<<<64, HID, 0, st>>>(out0, N1, ps, pq);
    bn_final<<<1, HID, 0, st>>>(ps, pq, (float)N1, mu, rstd);
    bn_apply<<<(N1 * HID + 255) / 256, 256, 0, st>>>(out0, N1, g0, be0, mu, rstd, 0);

    // ===== Layer 1: attention scores (emits oh) + softmax =====
    cmb_kernel<<<(HID * 40 * 32 + 255) / 256, 256, 0, st>>>(W1, as1, ad1, C, HID);
    tgemm<64><<<tg(N1, 40, 64), 256, 0, st>>>(out0, HID, 0, C, 0, SS, 40, 0, N1, 40, HID,
                                              nullptr, 0, oh);
    alphaA<<<(E1 + 255) / 256, 256, 0, st>>>(esort, bsorted, SS, alphas, E0, E1, NBINS0);
    denB<<<(NBINS1 + 255) / 256, 256, 0, st>>>(rp, alphas, den, NBINS0, NBINS1);

    // ===== Layer 1: aggregate + fp16 fused (head | skip) GEMM =====
    biasvec_kernel<<<1, HID, 0, st>>>(bsk1, b1, bias);
    aggx_kernel<HID><<<N2, HID / 4, 0, st>>>(rp + NBINS0, alphas, esort,
                                             den + (size_t)NBINS0 * 4, oh, aggX);
    prepack_h<<<(HEADS * ((RREL * HID + HID) / 2) * DH + 255) / 256, 256, 0, st>>>(
        W1, Wsk1, BcatP, HID, HID);
    hgemm<<<dim3((N2 + 127) / 128, HEADS), 256, HGH_SMEM, st>>>(
        aggX, HEADS * RREL * HID, (size_t)RREL * HID,
        oh, HID,
        BcatP, (size_t)((RREL * HID + HID) / 2) * DH,
        out1, HID, (size_t)DH,
        N2, RREL * HID, HID, bias);

    // ===== Layer 1: BN + ELU =====
    bn_stats<<<64, HID, 0, st>>>(out1, N2, ps, pq);
    bn_final<<<1, HID, 0, st>>>(ps, pq, (float)N2, mu, rstd);
    bn_apply<<<(N2 * HID + 255) / 256, 256, 0, st>>>(out1, N2, g1, be1, mu, rstd, 0);

    // ===== MLP head =====
    tgemm<128><<<tg(N2, HID, 128), 256, 0, st>>>(out1, HID, 0, Wm1, 0, z, HID, 0, N2, HID, HID,
                                                 bm1, 0, nullptr);
    bn_stats<<<64, HID, 0, st>>>(z, N2, ps, pq);
    bn_final<<<1, HID, 0, st>>>(ps, pq, (float)N2, mu, rstd);
    bn_apply<<<(N2 * HID + 255) / 256, 256, 0, st>>>(z, N2, gm, bmn, mu, rstd, 1);

    tgemm<64><<<tg(N2, OUTC, 64), 256, 0, st>>>(z, HID, 0, Wm2, 0, out, OUTC, 0, N2, OUTC, HID,
                                                bm2, 0, nullptr);
}